// round 3
// baseline (speedup 1.0000x reference)
#include <cuda_runtime.h>
#include <cstdint>
#include <math.h>

// ---------------------------------------------------------------------------
// Problem constants
// ---------------------------------------------------------------------------
#define B_ 16
#define T_ 64
#define NV 49
#define NN 50
#define H_ 512
#define H4 128            // H/4 (float4 units)
#define FRAMES (B_ * T_)                 // 1024
#define ROWS   (FRAMES * NN)             // 51200
#define TROWS  (B_ * (T_ - 1) * NN)      // 50400
#define NEGV   (-1.0e9f)

// Output layout: [out (ROWS*H)] [attn (FRAMES*NN*NN)] [cos (TROWS)]
#define OUT_MAIN ((size_t)ROWS * H_)          // 26214400
#define OUT_ATTN ((size_t)FRAMES * NN * NN)   // 2560000

// ---------------------------------------------------------------------------
// Scratch (device globals; no runtime allocation allowed)
// ---------------------------------------------------------------------------
__device__ float g_x[ROWS * H_];     // node features (layer input / output)
__device__ float g_sp[ROWS * H_];    // spatial (post LN+relu)
__device__ float g_P[ROWS * H_];     // gather buf / cos*prev / ln buf
__device__ float g_S[ROWS * H_];     // (1-cos)*cur
__device__ float g_C[ROWS * H_];     // tc, then tc+ts
__device__ float g_attn0[FRAMES * NN * NN];  // layer-0 attn (unused output)
__device__ float g_cos0[TROWS];              // layer-0 cos (unused output)

// ---------------------------------------------------------------------------
// Helpers
// ---------------------------------------------------------------------------
__device__ __forceinline__ float wred_sum(float v) {
    #pragma unroll
    for (int o = 16; o; o >>= 1) v += __shfl_xor_sync(0xffffffffu, v, o);
    return v;
}
__device__ __forceinline__ float wred_max(float v) {
    #pragma unroll
    for (int o = 16; o; o >>= 1) v = fmaxf(v, __shfl_xor_sync(0xffffffffu, v, o));
    return v;
}
__device__ __forceinline__ float dot4(float4 a, float4 b) {
    return a.x * b.x + a.y * b.y + a.z * b.z + a.w * b.w;
}
__device__ __forceinline__ bool window_allow(int i, int j) {
    // replicates _window_allow(49, 64, 7): r0 = clip(qr-1,0,61), c0 = clip(qc-1,0,4)
    int qr = i / 7, qc = i % 7;
    int kr = j / 7, kc = j % 7;
    int r0 = max(qr - 1, 0);
    int c0 = min(max(qc - 1, 0), 4);
    return (kr >= r0) && (kr <= r0 + 2) && (kc >= c0) && (kc <= c0 + 2) && (i != j);
}

// ---------------------------------------------------------------------------
// Gather: concat(visual, audio) -> [ROWS, H]
// ---------------------------------------------------------------------------
__global__ void __launch_bounds__(256) gather_k(
    const float* __restrict__ visual, const float* __restrict__ audio,
    float* __restrict__ out)
{
    int idx = blockIdx.x * blockDim.x + threadIdx.x;   // float4 index
    if (idx >= ROWS * H4) return;
    int m = idx >> 7;       // row
    int q = idx & 127;      // float4 col
    int i = m % NN;
    int bt = m / NN;        // b*T + t
    float4 v;
    if (i < NV) {
        v = ((const float4*)visual)[((size_t)bt * NV + i) * H4 + q];
    } else {
        v = ((const float4*)audio)[(size_t)bt * H4 + q];
    }
    ((float4*)out)[idx] = v;
}

// ---------------------------------------------------------------------------
// Per-frame attention + spatial aggregation + residual + LN + relu
// One block per frame (1024 blocks, 512 threads), whole frame in smem.
// ---------------------------------------------------------------------------
__global__ void __launch_bounds__(512) attn_k(
    const float* __restrict__ x, const float* __restrict__ edge,
    const float* __restrict__ lng, const float* __restrict__ lnb,
    float* __restrict__ spo, float* __restrict__ attn_out)
{
    extern __shared__ float sm[];
    float* xs   = sm;                  // NN*H
    float* spb  = xs + NN * H_;        // NN*H
    float* es   = spb + NN * H_;       // 3*H
    float* Smat = es + 3 * H_;         // NN*52 (padded stride)
    float* nx2  = Smat + NN * 52;      // NN
    float* d0   = nx2 + NN;            // NN
    float* d1   = d0 + NN;             // NN
    float* d2   = d1 + NN;             // NN
    float* rowsum = d2 + NN;           // NN
    float* ne   = rowsum + NN;         // 3

    const int tid = threadIdx.x;
    const int wid = tid >> 5, lane = tid & 31;
    const int f = blockIdx.x;

    float4* xs4 = (float4*)xs;
    float4* sp4 = (float4*)spb;
    float4* es4 = (float4*)es;
    const float4* xg = (const float4*)(x + (size_t)f * NN * H_);
    const float4* eg = (const float4*)edge;

    for (int i = tid; i < NN * H4; i += 512) xs4[i] = xg[i];
    for (int i = tid; i < 3 * H4; i += 512) es4[i] = eg[i];
    __syncthreads();

    // per-row dots: |x_i|^2, x_i.e0, x_i.e1, x_i.e2  (+ edge norms)
    for (int i = wid; i < NN + 3; i += 16) {
        if (i < NN) {
            float xx = 0.f, a0 = 0.f, a1 = 0.f, a2 = 0.f;
            for (int q = lane; q < H4; q += 32) {
                float4 xv = xs4[i * H4 + q];
                float4 e0v = es4[q], e1v = es4[H4 + q], e2v = es4[2 * H4 + q];
                xx += dot4(xv, xv);
                a0 += dot4(xv, e0v);
                a1 += dot4(xv, e1v);
                a2 += dot4(xv, e2v);
            }
            xx = wred_sum(xx); a0 = wred_sum(a0); a1 = wred_sum(a1); a2 = wred_sum(a2);
            if (lane == 0) { nx2[i] = xx; d0[i] = a0; d1[i] = a1; d2[i] = a2; }
        } else {
            int e = i - NN;
            float s = 0.f;
            for (int q = lane; q < H4; q += 32) { float4 ev = es4[e * H4 + q]; s += dot4(ev, ev); }
            s = wred_sum(s);
            if (lane == 0) ne[e] = s;
        }
    }
    __syncthreads();

    // scores (only unmasked entries compute a dot)
    for (int idx = tid; idx < NN * NN; idx += 512) {
        int i = idx / NN, j = idx % NN;
        bool masked;
        if (i == j) masked = true;
        else if (i < NV && j < NV) masked = !window_allow(i, j);
        else masked = false;   // row 49 (j<49) and col 49 (i<49) are open
        float v;
        if (masked) {
            v = NEGV;
        } else {
            float4 acc = make_float4(0.f, 0.f, 0.f, 0.f);
            const float4* xi = &xs4[i * H4];
            const float4* xj = &xs4[j * H4];
            #pragma unroll 4
            for (int q = 0; q < H4; q++) {
                float4 a = xi[q], b = xj[q];
                acc.x = fmaf(a.x, b.x, acc.x);
                acc.y = fmaf(a.y, b.y, acc.y);
                acc.z = fmaf(a.z, b.z, acc.z);
                acc.w = fmaf(a.w, b.w, acc.w);
            }
            float g = acc.x + acc.y + acc.z + acc.w;
            float num, qn2, kn2;
            if (i < NV && j < NV)      { num = g + d0[i];  qn2 = nx2[i];  kn2 = nx2[j]  + 2.f * d0[j]  + ne[0]; }
            else if (i == NV)          { num = g + d1[NV]; qn2 = nx2[NV]; kn2 = nx2[j]  + 2.f * d1[j]  + ne[1]; }
            else /* j == NV, i < NV */ { num = g + d2[i];  qn2 = nx2[i];  kn2 = nx2[NV] + 2.f * d2[NV] + ne[2]; }
            v = num / (fmaxf(sqrtf(qn2), 1e-12f) * fmaxf(sqrtf(kn2), 1e-12f));
        }
        Smat[i * 52 + j] = v;
    }
    __syncthreads();

    // softmax per row (warp per row) + write attn to global + rowsum over j<49
    for (int i = wid; i < NN; i += 16) {
        float v0 = (lane < NN) ? Smat[i * 52 + lane] : -3.0e38f;
        float v1 = (lane + 32 < NN) ? Smat[i * 52 + lane + 32] : -3.0e38f;
        float m = wred_max(fmaxf(v0, v1));
        float e0 = (lane < NN) ? expf(v0 - m) : 0.f;
        float e1 = (lane + 32 < NN) ? expf(v1 - m) : 0.f;
        float s = wred_sum(e0 + e1);
        float inv = 1.0f / s;
        float p0 = e0 * inv, p1 = e1 * inv;
        float rs = wred_sum(((lane < NV) ? p0 : 0.f) + ((lane + 32 < NV) ? p1 : 0.f));
        if (lane < NN) {
            Smat[i * 52 + lane] = p0;
            attn_out[(size_t)f * (NN * NN) + i * NN + lane] = p0;
        }
        if (lane + 32 < NN) {
            Smat[i * 52 + lane + 32] = p1;
            attn_out[(size_t)f * (NN * NN) + i * NN + lane + 32] = p1;
        }
        if (lane == 0) rowsum[i] = rs;
    }
    __syncthreads();

    // aggregation + residual:  sp = A@X + rowsum*e_sel + a49*(x49+e2) + x
    for (int idx = tid; idx < NN * H4; idx += 512) {
        int i = idx >> 7, q = idx & 127;
        const float* Ar = &Smat[i * 52];
        float4 acc = make_float4(0.f, 0.f, 0.f, 0.f);
        #pragma unroll 7
        for (int j = 0; j < NV; j++) {
            float a = Ar[j];
            float4 xv = xs4[j * H4 + q];
            acc.x = fmaf(a, xv.x, acc.x);
            acc.y = fmaf(a, xv.y, acc.y);
            acc.z = fmaf(a, xv.z, acc.z);
            acc.w = fmaf(a, xv.w, acc.w);
        }
        int sel = (i < NV) ? 0 : 1;
        float rs = rowsum[i];
        float4 ev = es4[sel * H4 + q];
        acc.x = fmaf(rs, ev.x, acc.x); acc.y = fmaf(rs, ev.y, acc.y);
        acc.z = fmaf(rs, ev.z, acc.z); acc.w = fmaf(rs, ev.w, acc.w);
        float a49 = Ar[NV];
        float4 x49 = xs4[NV * H4 + q];
        float4 e2v = es4[2 * H4 + q];
        acc.x = fmaf(a49, x49.x + e2v.x, acc.x);
        acc.y = fmaf(a49, x49.y + e2v.y, acc.y);
        acc.z = fmaf(a49, x49.z + e2v.z, acc.z);
        acc.w = fmaf(a49, x49.w + e2v.w, acc.w);
        float4 xi = xs4[i * H4 + q];   // residual
        acc.x += xi.x; acc.y += xi.y; acc.z += xi.z; acc.w += xi.w;
        sp4[idx] = acc;
    }
    __syncthreads();

    // layernorm + relu per row (warp per row), write to global
    for (int i = wid; i < NN; i += 16) {
        float4 v[4];
        #pragma unroll
        for (int c = 0; c < 4; c++) v[c] = sp4[i * H4 + lane + 32 * c];
        float s = 0.f;
        #pragma unroll
        for (int c = 0; c < 4; c++) s += v[c].x + v[c].y + v[c].z + v[c].w;
        float mean = wred_sum(s) * (1.0f / H_);
        float ss = 0.f;
        #pragma unroll
        for (int c = 0; c < 4; c++) {
            float dx = v[c].x - mean, dy = v[c].y - mean, dz = v[c].z - mean, dw = v[c].w - mean;
            ss += dx * dx + dy * dy + dz * dz + dw * dw;
        }
        float var = wred_sum(ss) * (1.0f / H_);
        float rstd = rsqrtf(var + 1e-5f);
        float4* og = (float4*)(spo + ((size_t)f * NN + i) * H_);
        #pragma unroll
        for (int c = 0; c < 4; c++) {
            int q = lane + 32 * c;
            float4 gv = ((const float4*)lng)[q];
            float4 bv = ((const float4*)lnb)[q];
            float4 o;
            o.x = fmaxf((v[c].x - mean) * rstd * gv.x + bv.x, 0.f);
            o.y = fmaxf((v[c].y - mean) * rstd * gv.y + bv.y, 0.f);
            o.z = fmaxf((v[c].z - mean) * rstd * gv.z + bv.z, 0.f);
            o.w = fmaxf((v[c].w - mean) * rstd * gv.w + bv.w, 0.f);
            og[q] = o;
        }
    }
}

// Smem bytes for attn_k
#define ATTN_SMEM ((2 * NN * H_ + 3 * H_ + NN * 52 + 5 * NN + 3 + 1) * 4)

// ---------------------------------------------------------------------------
// cos + build P = cos*prev, S = (1-cos)*cur   (one warp per temporal row)
// ---------------------------------------------------------------------------
__global__ void __launch_bounds__(256) cos_k(
    const float* __restrict__ sp, float* __restrict__ cosout,
    float* __restrict__ P, float* __restrict__ Sb)
{
    int gw = (blockIdx.x * blockDim.x + threadIdx.x) >> 5;
    int lane = threadIdx.x & 31;
    if (gw >= TROWS) return;
    int i = gw % NN;
    int bt = gw / NN;
    int b = bt / (T_ - 1);
    int tm1 = bt % (T_ - 1);       // = t-1
    const float4* cur  = (const float4*)(sp + ((size_t)(b * T_ + tm1 + 1) * NN + i) * H_);
    const float4* prev = (const float4*)(sp + ((size_t)(b * T_ + tm1) * NN + i) * H_);
    float dot = 0.f, na2 = 0.f, nb2 = 0.f;
    for (int q = lane; q < H4; q += 32) {
        float4 c = cur[q], p = prev[q];
        dot += dot4(c, p);
        na2 += dot4(c, c);
        nb2 += dot4(p, p);
    }
    dot = wred_sum(dot); na2 = wred_sum(na2); nb2 = wred_sum(nb2);
    float cosv = dot / (fmaxf(sqrtf(na2), 1e-8f) * fmaxf(sqrtf(nb2), 1e-8f));
    if (lane == 0) cosout[gw] = cosv;
    float omc = 1.0f - cosv;
    float4* Pr = (float4*)(P + (size_t)gw * H_);
    float4* Sr = (float4*)(Sb + (size_t)gw * H_);
    for (int q = lane; q < H4; q += 32) {
        float4 p = prev[q], c = cur[q];
        Pr[q] = make_float4(cosv * p.x, cosv * p.y, cosv * p.z, cosv * p.w);
        Sr[q] = make_float4(omc * c.x, omc * c.y, omc * c.z, omc * c.w);
    }
}

// ---------------------------------------------------------------------------
// assemble out_nodes = [spatial[:, :1], cur + (tc+ts)], then layernorm -> out
// one warp per row
// ---------------------------------------------------------------------------
__global__ void __launch_bounds__(256) assemble_k(
    const float* __restrict__ sp, const float* __restrict__ upd,
    const float* __restrict__ lng, const float* __restrict__ lnb,
    float* __restrict__ out)
{
    int m = (blockIdx.x * blockDim.x + threadIdx.x) >> 5;
    int lane = threadIdx.x & 31;
    if (m >= ROWS) return;
    int i = m % NN;
    int t = (m / NN) % T_;
    int b = m / (NN * T_);
    const float4* s = (const float4*)(sp + (size_t)m * H_);
    float4 v[4];
    #pragma unroll
    for (int c = 0; c < 4; c++) v[c] = s[lane + 32 * c];
    if (t > 0) {
        size_t r = (size_t)(b * (T_ - 1) + (t - 1)) * NN + i;
        const float4* u = (const float4*)(upd + r * H_);
        #pragma unroll
        for (int c = 0; c < 4; c++) {
            float4 uu = u[lane + 32 * c];
            v[c].x += uu.x; v[c].y += uu.y; v[c].z += uu.z; v[c].w += uu.w;
        }
    }
    float sum = 0.f;
    #pragma unroll
    for (int c = 0; c < 4; c++) sum += v[c].x + v[c].y + v[c].z + v[c].w;
    float mean = wred_sum(sum) * (1.0f / H_);
    float ss = 0.f;
    #pragma unroll
    for (int c = 0; c < 4; c++) {
        float dx = v[c].x - mean, dy = v[c].y - mean, dz = v[c].z - mean, dw = v[c].w - mean;
        ss += dx * dx + dy * dy + dz * dz + dw * dw;
    }
    float var = wred_sum(ss) * (1.0f / H_);
    float rstd = rsqrtf(var + 1e-5f);
    float4* o = (float4*)(out + (size_t)m * H_);
    #pragma unroll
    for (int c = 0; c < 4; c++) {
        int q = lane + 32 * c;
        float4 gv = ((const float4*)lng)[q];
        float4 bv = ((const float4*)lnb)[q];
        float4 r;
        r.x = (v[c].x - mean) * rstd * gv.x + bv.x;
        r.y = (v[c].y - mean) * rstd * gv.y + bv.y;
        r.z = (v[c].z - mean) * rstd * gv.z + bv.z;
        r.w = (v[c].w - mean) * rstd * gv.w + bv.w;
        o[q] = r;
    }
}

// ---------------------------------------------------------------------------
// SGEMM: C = epilogue(A[M,512] @ W[512,512]^T)
// 2-stage: register prefetch + double-buffered smem (ONE barrier per k-tile)
//   MODE 0: + bias
//   MODE 1: relu(+bias)
//   MODE 2: D1 + relu(+bias)
//   MODE 3: D1 + relu(.)         (no bias)
// ---------------------------------------------------------------------------
template <int MODE>
__global__ void __launch_bounds__(256, 2) sgemm_k(
    const float* __restrict__ A, const float* __restrict__ Wt,
    const float* __restrict__ bias, const float* __restrict__ D1,
    float* __restrict__ C, int M)
{
    const int K = 512, N = 512;
    __shared__ float As[2][16][128];
    __shared__ float Bs[2][16][128];
    int m0 = blockIdx.y * 128, n0 = blockIdx.x * 128;
    int tid = threadIdx.x;
    int ty = tid >> 4, tx = tid & 15;
    int lrow = tid >> 2, lc4 = tid & 3;
    float acc[8][8];
    #pragma unroll
    for (int i = 0; i < 8; i++)
        #pragma unroll
        for (int j = 0; j < 8; j++) acc[i][j] = 0.f;

    float4 pa[2], pb[2];
    // prologue: load k-tile 0 into registers, stage into buffer 0
    #pragma unroll
    for (int q = 0; q < 2; q++) {
        int r = lrow + q * 64;
        int gm = m0 + r;
        pa[q] = make_float4(0.f, 0.f, 0.f, 0.f);
        if (gm < M) pa[q] = *(const float4*)(A + (size_t)gm * K + lc4 * 4);
        pb[q] = *(const float4*)(Wt + (size_t)(n0 + r) * K + lc4 * 4);
    }
    #pragma unroll
    for (int q = 0; q < 2; q++) {
        int r = lrow + q * 64;
        As[0][lc4 * 4 + 0][r] = pa[q].x; As[0][lc4 * 4 + 1][r] = pa[q].y;
        As[0][lc4 * 4 + 2][r] = pa[q].z; As[0][lc4 * 4 + 3][r] = pa[q].w;
        Bs[0][lc4 * 4 + 0][r] = pb[q].x; Bs[0][lc4 * 4 + 1][r] = pb[q].y;
        Bs[0][lc4 * 4 + 2][r] = pb[q].z; Bs[0][lc4 * 4 + 3][r] = pb[q].w;
    }
    __syncthreads();

    int p = 0;
    for (int kt = 0; kt < K; kt += 16) {
        bool more = (kt + 16 < K);
        // prefetch next k-tile into registers (overlaps with FMA block)
        if (more) {
            #pragma unroll
            for (int q = 0; q < 2; q++) {
                int r = lrow + q * 64;
                int gm = m0 + r;
                pa[q] = make_float4(0.f, 0.f, 0.f, 0.f);
                if (gm < M) pa[q] = *(const float4*)(A + (size_t)gm * K + kt + 16 + lc4 * 4);
                pb[q] = *(const float4*)(Wt + (size_t)(n0 + r) * K + kt + 16 + lc4 * 4);
            }
        }

        #pragma unroll
        for (int kk = 0; kk < 16; kk++) {
            float a[8], b[8];
            *(float4*)&a[0] = *(const float4*)&As[p][kk][ty * 8];
            *(float4*)&a[4] = *(const float4*)&As[p][kk][ty * 8 + 4];
            *(float4*)&b[0] = *(const float4*)&Bs[p][kk][tx * 8];
            *(float4*)&b[4] = *(const float4*)&Bs[p][kk][tx * 8 + 4];
            #pragma unroll
            for (int i = 0; i < 8; i++)
                #pragma unroll
                for (int j = 0; j < 8; j++)
                    acc[i][j] = fmaf(a[i], b[j], acc[i][j]);
        }

        if (more) {
            int np = p ^ 1;
            #pragma unroll
            for (int q = 0; q < 2; q++) {
                int r = lrow + q * 64;
                As[np][lc4 * 4 + 0][r] = pa[q].x; As[np][lc4 * 4 + 1][r] = pa[q].y;
                As[np][lc4 * 4 + 2][r] = pa[q].z; As[np][lc4 * 4 + 3][r] = pa[q].w;
                Bs[np][lc4 * 4 + 0][r] = pb[q].x; Bs[np][lc4 * 4 + 1][r] = pb[q].y;
                Bs[np][lc4 * 4 + 2][r] = pb[q].z; Bs[np][lc4 * 4 + 3][r] = pb[q].w;
            }
            __syncthreads();
            p = np;
        }
    }

    #pragma unroll
    for (int i = 0; i < 8; i++) {
        int gm = m0 + ty * 8 + i;
        if (gm >= M) continue;
        #pragma unroll
        for (int j = 0; j < 8; j += 4) {
            int gn = n0 + tx * 8 + j;
            float4 v = make_float4(acc[i][j], acc[i][j + 1], acc[i][j + 2], acc[i][j + 3]);
            if (MODE == 0 || MODE == 1 || MODE == 2) {
                float4 bb = *(const float4*)(bias + gn);
                v.x += bb.x; v.y += bb.y; v.z += bb.z; v.w += bb.w;
            }
            if (MODE >= 1) {
                v.x = fmaxf(v.x, 0.f); v.y = fmaxf(v.y, 0.f);
                v.z = fmaxf(v.z, 0.f); v.w = fmaxf(v.w, 0.f);
            }
            if (MODE == 2 || MODE == 3) {
                float4 d = *(const float4*)(D1 + (size_t)gm * N + gn);
                v.x += d.x; v.y += d.y; v.z += d.z; v.w += d.w;
            }
            *(float4*)(C + (size_t)gm * N + gn) = v;
        }
    }
}

// ---------------------------------------------------------------------------
// Launch
// ---------------------------------------------------------------------------
extern "C" void kernel_launch(void* const* d_in, const int* in_sizes, int n_in,
                              void* d_out, int out_size)
{
    const float* visual = (const float*)d_in[0];
    const float* audio  = (const float*)d_in[1];
    const float* in_W   = (const float*)d_in[2];
    const float* in_b   = (const float*)d_in[3];
    const float* out_W  = (const float*)d_in[4];
    const float* out_b  = (const float*)d_in[5];

    float *x, *sp, *P, *S, *C, *attn0, *cos0;
    cudaGetSymbolAddress((void**)&x, g_x);
    cudaGetSymbolAddress((void**)&sp, g_sp);
    cudaGetSymbolAddress((void**)&P, g_P);
    cudaGetSymbolAddress((void**)&S, g_S);
    cudaGetSymbolAddress((void**)&C, g_C);
    cudaGetSymbolAddress((void**)&attn0, g_attn0);
    cudaGetSymbolAddress((void**)&cos0, g_cos0);

    cudaFuncSetAttribute(attn_k, cudaFuncAttributeMaxDynamicSharedMemorySize, ATTN_SMEM);

    float* outp = (float*)d_out;

    dim3 gfull(4, (ROWS + 127) / 128);
    dim3 gtemp(4, (TROWS + 127) / 128);

    // input projection
    {
        int nthr = 256;
        int nblk = (ROWS * H4 + nthr - 1) / nthr;
        gather_k<<<nblk, nthr>>>(visual, audio, P);
        sgemm_k<0><<<gfull, 256>>>(P, in_W, in_b, nullptr, x, ROWS);
    }

    for (int layer = 0; layer < 2; layer++) {
        const float* edge = (const float*)d_in[6 + 8 * layer];
        const float* lng  = (const float*)d_in[7 + 8 * layer];
        const float* lnb  = (const float*)d_in[8 + 8 * layer];
        const float* Wc   = (const float*)d_in[9 + 8 * layer];
        const float* bc   = (const float*)d_in[10 + 8 * layer];
        const float* Ws   = (const float*)d_in[11 + 8 * layer];
        const float* bs   = (const float*)d_in[12 + 8 * layer];
        const float* Wo   = (const float*)d_in[13 + 8 * layer];

        float* attn_out = (layer == 1) ? (outp + OUT_MAIN) : attn0;
        float* cos_out  = (layer == 1) ? (outp + OUT_MAIN + OUT_ATTN) : cos0;

        attn_k<<<FRAMES, 512, ATTN_SMEM>>>(x, edge, lng, lnb, sp, attn_out);

        {
            int nblk = (TROWS * 32 + 255) / 256;
            cos_k<<<nblk, 256>>>(sp, cos_out, P, S);
        }

        sgemm_k<1><<<gtemp, 256>>>(P, Wc, bc, nullptr, C, TROWS);   // C = relu(P@Wc^T+bc)
        sgemm_k<2><<<gtemp, 256>>>(S, Ws, bs, C, C, TROWS);         // C = C + relu(S@Ws^T+bs)

        {
            int nblk = (ROWS * 32 + 255) / 256;
            assemble_k<<<nblk, 256>>>(sp, C, lng, lnb, P);          // P = LN(out_nodes)
        }

        sgemm_k<3><<<gfull, 256>>>(P, Wo, nullptr, x, x, ROWS);     // x = x + relu(P@Wo^T)
    }

    // output projection -> d_out main region
    sgemm_k<0><<<gfull, 256>>>(x, out_W, out_b, nullptr, outp, ROWS);

    (void)in_sizes; (void)n_in; (void)out_size;
}

// round 5
// speedup vs baseline: 1.8148x; 1.8148x over previous
#include <cuda_runtime.h>
#include <cuda_bf16.h>
#include <cstdint>
#include <math.h>

// ---------------------------------------------------------------------------
// Problem constants
// ---------------------------------------------------------------------------
#define B_ 16
#define T_ 64
#define NV 49
#define NN 50
#define H_ 512
#define H4 128            // H/4 (float4 units)
#define FRAMES (B_ * T_)                 // 1024
#define ROWS   (FRAMES * NN)             // 51200
#define TROWS  (B_ * (T_ - 1) * NN)      // 50400
#define NEGV   (-1.0e9f)

// Output layout: [out (ROWS*H)] [attn (FRAMES*NN*NN)] [cos (TROWS)]
#define OUT_MAIN ((size_t)ROWS * H_)
#define OUT_ATTN ((size_t)FRAMES * NN * NN)

// ---------------------------------------------------------------------------
// Scratch (device globals; no runtime allocation allowed)
// ---------------------------------------------------------------------------
__device__ float g_x[ROWS * H_];
__device__ float g_sp[ROWS * H_];
__device__ float g_P[ROWS * H_];
__device__ float g_S[ROWS * H_];
__device__ float g_C[ROWS * H_];
__device__ float g_attn0[FRAMES * NN * NN];
__device__ float g_cos0[TROWS];

// ---------------------------------------------------------------------------
// Generic helpers
// ---------------------------------------------------------------------------
__device__ __forceinline__ float wred_sum(float v) {
    #pragma unroll
    for (int o = 16; o; o >>= 1) v += __shfl_xor_sync(0xffffffffu, v, o);
    return v;
}
__device__ __forceinline__ float wred_max(float v) {
    #pragma unroll
    for (int o = 16; o; o >>= 1) v = fmaxf(v, __shfl_xor_sync(0xffffffffu, v, o));
    return v;
}
__device__ __forceinline__ float dot4(float4 a, float4 b) {
    return a.x * b.x + a.y * b.y + a.z * b.z + a.w * b.w;
}
__device__ __forceinline__ bool window_allow(int i, int j) {
    int qr = i / 7, qc = i % 7;
    int kr = j / 7, kc = j % 7;
    int r0 = max(qr - 1, 0);
    int c0 = min(max(qc - 1, 0), 4);
    return (kr >= r0) && (kr <= r0 + 2) && (kc >= c0) && (kc <= c0 + 2) && (i != j);
}
__device__ __forceinline__ uint32_t smem_u32(const void* p) {
    uint32_t a;
    asm("{ .reg .u64 t; cvta.to.shared.u64 t, %1; cvt.u32.u64 %0, t; }" : "=r"(a) : "l"(p));
    return a;
}
__device__ __forceinline__ uint32_t pkbf(__nv_bfloat16 a, __nv_bfloat16 b) {
    return (uint32_t)__bfloat16_as_ushort(a) | ((uint32_t)__bfloat16_as_ushort(b) << 16);
}

// ---------------------------------------------------------------------------
// mma.sync helpers (sm_80+ PTX; works on plain sm_103 target)
// ---------------------------------------------------------------------------
__device__ __forceinline__ void ldsm4(uint32_t r[4], uint32_t addr) {
    asm volatile("ldmatrix.sync.aligned.m8n8.x4.shared.b16 {%0,%1,%2,%3}, [%4];"
                 : "=r"(r[0]), "=r"(r[1]), "=r"(r[2]), "=r"(r[3]) : "r"(addr));
}
__device__ __forceinline__ void mma16816(float c[4], const uint32_t a[4],
                                         uint32_t b0, uint32_t b1) {
    asm volatile(
        "mma.sync.aligned.m16n8k16.row.col.f32.bf16.bf16.f32 "
        "{%0,%1,%2,%3}, {%4,%5,%6,%7}, {%8,%9}, {%0,%1,%2,%3};"
        : "+f"(c[0]), "+f"(c[1]), "+f"(c[2]), "+f"(c[3])
        : "r"(a[0]), "r"(a[1]), "r"(a[2]), "r"(a[3]), "r"(b0), "r"(b1));
}

// ---------------------------------------------------------------------------
// bf16x3 tensor GEMM: C[M,512] = epi(A[M,512] @ W[512,512]^T)
//   MODE 0: + bias | 1: relu(+bias) | 2: D1 + relu(+bias) | 3: D1 + relu(.)
// Block tile 128x128, 256 thr (8 warps 2x4), warp tile 64x32, K-chunk 32.
// ---------------------------------------------------------------------------
#define LSTR 40                    // bf16 elems per smem row (80 B)
#define TILE_ELEMS (128 * LSTR)    // 5120 bf16 per sub-tile
#define OFF_AH 0
#define OFF_AL (TILE_ELEMS * 2)        // bytes
#define OFF_BH (TILE_ELEMS * 4)
#define OFF_BL (TILE_ELEMS * 6)

template <int MODE>
__global__ void __launch_bounds__(256, 2) mmagemm_k(
    const float* __restrict__ A, const float* __restrict__ W,
    const float* __restrict__ bias, const float* __restrict__ D1,
    float* __restrict__ C, int M)
{
    __shared__ __align__(16) __nv_bfloat16 smem[4 * TILE_ELEMS];   // 40 KB
    const uint32_t sb = smem_u32(smem);

    const int tid = threadIdx.x;
    const int lane = tid & 31, wid = tid >> 5;
    const int wm = wid >> 2, wn = wid & 3;            // 2 x 4 warp grid
    const int m0 = blockIdx.y * 128, n0 = blockIdx.x * 128;

    float acc[4][4][4];
    #pragma unroll
    for (int a = 0; a < 4; a++)
        #pragma unroll
        for (int b = 0; b < 4; b++)
            #pragma unroll
            for (int c = 0; c < 4; c++) acc[a][b][c] = 0.f;

    // global load mapping: thread covers half of one A row + half of one B row
    const int lrow = tid >> 1;
    const int lhalf = tid & 1;
    const bool av = (m0 + lrow) < M;
    const float* ap = A + (size_t)(m0 + lrow) * 512 + lhalf * 16;
    const float* bp = W + (size_t)(n0 + lrow) * 512 + lhalf * 16;
    const uint32_t st_byte = ((uint32_t)lrow * LSTR + (uint32_t)lhalf * 16) * 2;

    // ldmatrix per-lane offsets (bytes)
    const uint32_t a_off =
        (((uint32_t)(wm * 64 + (((lane >> 3) & 1) << 3) + (lane & 7))) * LSTR +
         (((lane >> 4) & 1) << 3)) * 2;
    const uint32_t b_off =
        (((uint32_t)(wn * 32 + (((lane >> 4) & 1) << 3) + (lane & 7))) * LSTR +
         (((lane >> 3) & 1) << 3)) * 2;

    #pragma unroll 1
    for (int ck = 0; ck < 16; ck++) {
        // ------- load + convert fp32 -> (hi, lo) bf16 into smem -------
        #pragma unroll
        for (int mtx = 0; mtx < 2; mtx++) {
            const float* p = (mtx == 0) ? (ap + ck * 32) : (bp + ck * 32);
            const bool vld = (mtx == 0) ? av : true;
            char* hb = (char*)smem + (mtx == 0 ? OFF_AH : OFF_BH) + st_byte;
            char* lb = (char*)smem + (mtx == 0 ? OFF_AL : OFF_BL) + st_byte;
            float v[16];
            #pragma unroll
            for (int j = 0; j < 4; j++) {
                float4 f = vld ? *(const float4*)(p + j * 4)
                               : make_float4(0.f, 0.f, 0.f, 0.f);
                v[j * 4 + 0] = f.x; v[j * 4 + 1] = f.y;
                v[j * 4 + 2] = f.z; v[j * 4 + 3] = f.w;
            }
            uint32_t h[8], l[8];
            #pragma unroll
            for (int e = 0; e < 8; e++) {
                __nv_bfloat16 h0 = __float2bfloat16_rn(v[2 * e]);
                __nv_bfloat16 h1 = __float2bfloat16_rn(v[2 * e + 1]);
                __nv_bfloat16 l0 = __float2bfloat16_rn(v[2 * e] - __bfloat162float(h0));
                __nv_bfloat16 l1 = __float2bfloat16_rn(v[2 * e + 1] - __bfloat162float(h1));
                h[e] = pkbf(h0, h1);
                l[e] = pkbf(l0, l1);
            }
            *(uint4*)(hb) = make_uint4(h[0], h[1], h[2], h[3]);
            *(uint4*)(hb + 16) = make_uint4(h[4], h[5], h[6], h[7]);
            *(uint4*)(lb) = make_uint4(l[0], l[1], l[2], l[3]);
            *(uint4*)(lb + 16) = make_uint4(l[4], l[5], l[6], l[7]);
        }
        __syncthreads();

        // ------- tensor-core compute: (Ah,Bh), (Ah,Bl), (Al,Bh) -------
        #pragma unroll
        for (int ks = 0; ks < 2; ks++) {
            const uint32_t kb = (uint32_t)ks * 32;   // 16 bf16 = 32 bytes
            #pragma unroll
            for (int combo = 0; combo < 3; combo++) {
                const uint32_t apart = (combo == 2) ? OFF_AL : OFF_AH;
                const uint32_t bpart = (combo == 1) ? OFF_BL : OFF_BH;
                uint32_t af[4][4], bfr[2][4];
                #pragma unroll
                for (int mt = 0; mt < 4; mt++)
                    ldsm4(af[mt], sb + apart + a_off + (uint32_t)mt * (16 * LSTR * 2) + kb);
                #pragma unroll
                for (int p = 0; p < 2; p++)
                    ldsm4(bfr[p], sb + bpart + b_off + (uint32_t)p * (16 * LSTR * 2) + kb);
                #pragma unroll
                for (int mt = 0; mt < 4; mt++)
                    #pragma unroll
                    for (int p = 0; p < 2; p++) {
                        mma16816(acc[mt][p * 2 + 0], af[mt], bfr[p][0], bfr[p][1]);
                        mma16816(acc[mt][p * 2 + 1], af[mt], bfr[p][2], bfr[p][3]);
                    }
            }
        }
        __syncthreads();
    }

    // ------- epilogue -------
    const int r = lane >> 2;
    const int cc = (lane & 3) * 2;
    #pragma unroll
    for (int mt = 0; mt < 4; mt++) {
        #pragma unroll
        for (int nt = 0; nt < 4; nt++) {
            const int gm = m0 + wm * 64 + mt * 16 + r;
            const int gn = n0 + wn * 32 + nt * 8 + cc;
            float2 bb = make_float2(0.f, 0.f);
            if (MODE == 0 || MODE == 1 || MODE == 2) bb = *(const float2*)(bias + gn);
            #pragma unroll
            for (int h = 0; h < 2; h++) {
                const int gmr = gm + h * 8;
                if (gmr >= M) continue;
                float2 v = make_float2(acc[mt][nt][h * 2 + 0], acc[mt][nt][h * 2 + 1]);
                if (MODE == 0 || MODE == 1 || MODE == 2) { v.x += bb.x; v.y += bb.y; }
                if (MODE >= 1) { v.x = fmaxf(v.x, 0.f); v.y = fmaxf(v.y, 0.f); }
                if (MODE == 2 || MODE == 3) {
                    float2 d = *(const float2*)(D1 + (size_t)gmr * 512 + gn);
                    v.x += d.x; v.y += d.y;
                }
                *(float2*)(C + (size_t)gmr * 512 + gn) = v;
            }
        }
    }
}

// ---------------------------------------------------------------------------
// Gather: concat(visual, audio) -> [ROWS, H]
// ---------------------------------------------------------------------------
__global__ void __launch_bounds__(256) gather_k(
    const float* __restrict__ visual, const float* __restrict__ audio,
    float* __restrict__ out)
{
    int idx = blockIdx.x * blockDim.x + threadIdx.x;
    if (idx >= ROWS * H4) return;
    int m = idx >> 7;
    int q = idx & 127;
    int i = m % NN;
    int bt = m / NN;
    float4 v;
    if (i < NV) {
        v = ((const float4*)visual)[((size_t)bt * NV + i) * H4 + q];
    } else {
        v = ((const float4*)audio)[(size_t)bt * H4 + q];
    }
    ((float4*)out)[idx] = v;
}

// ---------------------------------------------------------------------------
// Per-frame attention + aggregation + residual + LN + relu
// ---------------------------------------------------------------------------
__global__ void __launch_bounds__(512) attn_k(
    const float* __restrict__ x, const float* __restrict__ edge,
    const float* __restrict__ lng, const float* __restrict__ lnb,
    float* __restrict__ spo, float* __restrict__ attn_out)
{
    extern __shared__ float sm[];
    float* xs   = sm;
    float* spb  = xs + NN * H_;
    float* es   = spb + NN * H_;
    float* Smat = es + 3 * H_;
    float* nx2  = Smat + NN * 52;
    float* d0   = nx2 + NN;
    float* d1   = d0 + NN;
    float* d2   = d1 + NN;
    float* rowsum = d2 + NN;
    float* ne   = rowsum + NN;

    const int tid = threadIdx.x;
    const int wid = tid >> 5, lane = tid & 31;
    const int f = blockIdx.x;

    float4* xs4 = (float4*)xs;
    float4* sp4 = (float4*)spb;
    float4* es4 = (float4*)es;
    const float4* xg = (const float4*)(x + (size_t)f * NN * H_);
    const float4* eg = (const float4*)edge;

    for (int i = tid; i < NN * H4; i += 512) xs4[i] = xg[i];
    for (int i = tid; i < 3 * H4; i += 512) es4[i] = eg[i];
    __syncthreads();

    for (int i = wid; i < NN + 3; i += 16) {
        if (i < NN) {
            float xx = 0.f, a0 = 0.f, a1 = 0.f, a2 = 0.f;
            for (int q = lane; q < H4; q += 32) {
                float4 xv = xs4[i * H4 + q];
                float4 e0v = es4[q], e1v = es4[H4 + q], e2v = es4[2 * H4 + q];
                xx += dot4(xv, xv);
                a0 += dot4(xv, e0v);
                a1 += dot4(xv, e1v);
                a2 += dot4(xv, e2v);
            }
            xx = wred_sum(xx); a0 = wred_sum(a0); a1 = wred_sum(a1); a2 = wred_sum(a2);
            if (lane == 0) { nx2[i] = xx; d0[i] = a0; d1[i] = a1; d2[i] = a2; }
        } else {
            int e = i - NN;
            float s = 0.f;
            for (int q = lane; q < H4; q += 32) { float4 ev = es4[e * H4 + q]; s += dot4(ev, ev); }
            s = wred_sum(s);
            if (lane == 0) ne[e] = s;
        }
    }
    __syncthreads();

    for (int idx = tid; idx < NN * NN; idx += 512) {
        int i = idx / NN, j = idx % NN;
        bool masked;
        if (i == j) masked = true;
        else if (i < NV && j < NV) masked = !window_allow(i, j);
        else masked = false;
        float v;
        if (masked) {
            v = NEGV;
        } else {
            float4 acc = make_float4(0.f, 0.f, 0.f, 0.f);
            const float4* xi = &xs4[i * H4];
            const float4* xj = &xs4[j * H4];
            #pragma unroll 4
            for (int q = 0; q < H4; q++) {
                float4 a = xi[q], b = xj[q];
                acc.x = fmaf(a.x, b.x, acc.x);
                acc.y = fmaf(a.y, b.y, acc.y);
                acc.z = fmaf(a.z, b.z, acc.z);
                acc.w = fmaf(a.w, b.w, acc.w);
            }
            float g = acc.x + acc.y + acc.z + acc.w;
            float num, qn2, kn2;
            if (i < NV && j < NV)      { num = g + d0[i];  qn2 = nx2[i];  kn2 = nx2[j]  + 2.f * d0[j]  + ne[0]; }
            else if (i == NV)          { num = g + d1[NV]; qn2 = nx2[NV]; kn2 = nx2[j]  + 2.f * d1[j]  + ne[1]; }
            else                       { num = g + d2[i];  qn2 = nx2[i];  kn2 = nx2[NV] + 2.f * d2[NV] + ne[2]; }
            v = num / (fmaxf(sqrtf(qn2), 1e-12f) * fmaxf(sqrtf(kn2), 1e-12f));
        }
        Smat[i * 52 + j] = v;
    }
    __syncthreads();

    for (int i = wid; i < NN; i += 16) {
        float v0 = (lane < NN) ? Smat[i * 52 + lane] : -3.0e38f;
        float v1 = (lane + 32 < NN) ? Smat[i * 52 + lane + 32] : -3.0e38f;
        float m = wred_max(fmaxf(v0, v1));
        float e0 = (lane < NN) ? expf(v0 - m) : 0.f;
        float e1 = (lane + 32 < NN) ? expf(v1 - m) : 0.f;
        float s = wred_sum(e0 + e1);
        float inv = 1.0f / s;
        float p0 = e0 * inv, p1 = e1 * inv;
        float rs = wred_sum(((lane < NV) ? p0 : 0.f) + ((lane + 32 < NV) ? p1 : 0.f));
        if (lane < NN) {
            Smat[i * 52 + lane] = p0;
            attn_out[(size_t)f * (NN * NN) + i * NN + lane] = p0;
        }
        if (lane + 32 < NN) {
            Smat[i * 52 + lane + 32] = p1;
            attn_out[(size_t)f * (NN * NN) + i * NN + lane + 32] = p1;
        }
        if (lane == 0) rowsum[i] = rs;
    }
    __syncthreads();

    for (int idx = tid; idx < NN * H4; idx += 512) {
        int i = idx >> 7, q = idx & 127;
        const float* Ar = &Smat[i * 52];
        float4 acc = make_float4(0.f, 0.f, 0.f, 0.f);
        #pragma unroll 7
        for (int j = 0; j < NV; j++) {
            float a = Ar[j];
            float4 xv = xs4[j * H4 + q];
            acc.x = fmaf(a, xv.x, acc.x);
            acc.y = fmaf(a, xv.y, acc.y);
            acc.z = fmaf(a, xv.z, acc.z);
            acc.w = fmaf(a, xv.w, acc.w);
        }
        int sel = (i < NV) ? 0 : 1;
        float rs = rowsum[i];
        float4 ev = es4[sel * H4 + q];
        acc.x = fmaf(rs, ev.x, acc.x); acc.y = fmaf(rs, ev.y, acc.y);
        acc.z = fmaf(rs, ev.z, acc.z); acc.w = fmaf(rs, ev.w, acc.w);
        float a49 = Ar[NV];
        float4 x49 = xs4[NV * H4 + q];
        float4 e2v = es4[2 * H4 + q];
        acc.x = fmaf(a49, x49.x + e2v.x, acc.x);
        acc.y = fmaf(a49, x49.y + e2v.y, acc.y);
        acc.z = fmaf(a49, x49.z + e2v.z, acc.z);
        acc.w = fmaf(a49, x49.w + e2v.w, acc.w);
        float4 xi = xs4[i * H4 + q];
        acc.x += xi.x; acc.y += xi.y; acc.z += xi.z; acc.w += xi.w;
        sp4[idx] = acc;
    }
    __syncthreads();

    for (int i = wid; i < NN; i += 16) {
        float4 v[4];
        #pragma unroll
        for (int c = 0; c < 4; c++) v[c] = sp4[i * H4 + lane + 32 * c];
        float s = 0.f;
        #pragma unroll
        for (int c = 0; c < 4; c++) s += v[c].x + v[c].y + v[c].z + v[c].w;
        float mean = wred_sum(s) * (1.0f / H_);
        float ss = 0.f;
        #pragma unroll
        for (int c = 0; c < 4; c++) {
            float dx = v[c].x - mean, dy = v[c].y - mean, dz = v[c].z - mean, dw = v[c].w - mean;
            ss += dx * dx + dy * dy + dz * dz + dw * dw;
        }
        float var = wred_sum(ss) * (1.0f / H_);
        float rstd = rsqrtf(var + 1e-5f);
        float4* og = (float4*)(spo + ((size_t)f * NN + i) * H_);
        #pragma unroll
        for (int c = 0; c < 4; c++) {
            int q = lane + 32 * c;
            float4 gv = ((const float4*)lng)[q];
            float4 bv = ((const float4*)lnb)[q];
            float4 o;
            o.x = fmaxf((v[c].x - mean) * rstd * gv.x + bv.x, 0.f);
            o.y = fmaxf((v[c].y - mean) * rstd * gv.y + bv.y, 0.f);
            o.z = fmaxf((v[c].z - mean) * rstd * gv.z + bv.z, 0.f);
            o.w = fmaxf((v[c].w - mean) * rstd * gv.w + bv.w, 0.f);
            og[q] = o;
        }
    }
}

#define ATTN_SMEM ((2 * NN * H_ + 3 * H_ + NN * 52 + 5 * NN + 3 + 1) * 4)

// ---------------------------------------------------------------------------
// cos + build P = cos*prev, S = (1-cos)*cur
// ---------------------------------------------------------------------------
__global__ void __launch_bounds__(256) cos_k(
    const float* __restrict__ sp, float* __restrict__ cosout,
    float* __restrict__ P, float* __restrict__ Sb)
{
    int gw = (blockIdx.x * blockDim.x + threadIdx.x) >> 5;
    int lane = threadIdx.x & 31;
    if (gw >= TROWS) return;
    int i = gw % NN;
    int bt = gw / NN;
    int b = bt / (T_ - 1);
    int tm1 = bt % (T_ - 1);
    const float4* cur  = (const float4*)(sp + ((size_t)(b * T_ + tm1 + 1) * NN + i) * H_);
    const float4* prev = (const float4*)(sp + ((size_t)(b * T_ + tm1) * NN + i) * H_);
    float dot = 0.f, na2 = 0.f, nb2 = 0.f;
    for (int q = lane; q < H4; q += 32) {
        float4 c = cur[q], p = prev[q];
        dot += dot4(c, p);
        na2 += dot4(c, c);
        nb2 += dot4(p, p);
    }
    dot = wred_sum(dot); na2 = wred_sum(na2); nb2 = wred_sum(nb2);
    float cosv = dot / (fmaxf(sqrtf(na2), 1e-8f) * fmaxf(sqrtf(nb2), 1e-8f));
    if (lane == 0) cosout[gw] = cosv;
    float omc = 1.0f - cosv;
    float4* Pr = (float4*)(P + (size_t)gw * H_);
    float4* Sr = (float4*)(Sb + (size_t)gw * H_);
    for (int q = lane; q < H4; q += 32) {
        float4 p = prev[q], c = cur[q];
        Pr[q] = make_float4(cosv * p.x, cosv * p.y, cosv * p.z, cosv * p.w);
        Sr[q] = make_float4(omc * c.x, omc * c.y, omc * c.z, omc * c.w);
    }
}

// ---------------------------------------------------------------------------
// assemble + layernorm
// ---------------------------------------------------------------------------
__global__ void __launch_bounds__(256) assemble_k(
    const float* __restrict__ sp, const float* __restrict__ upd,
    const float* __restrict__ lng, const float* __restrict__ lnb,
    float* __restrict__ out)
{
    int m = (blockIdx.x * blockDim.x + threadIdx.x) >> 5;
    int lane = threadIdx.x & 31;
    if (m >= ROWS) return;
    int i = m % NN;
    int t = (m / NN) % T_;
    int b = m / (NN * T_);
    const float4* s = (const float4*)(sp + (size_t)m * H_);
    float4 v[4];
    #pragma unroll
    for (int c = 0; c < 4; c++) v[c] = s[lane + 32 * c];
    if (t > 0) {
        size_t r = (size_t)(b * (T_ - 1) + (t - 1)) * NN + i;
        const float4* u = (const float4*)(upd + r * H_);
        #pragma unroll
        for (int c = 0; c < 4; c++) {
            float4 uu = u[lane + 32 * c];
            v[c].x += uu.x; v[c].y += uu.y; v[c].z += uu.z; v[c].w += uu.w;
        }
    }
    float sum = 0.f;
    #pragma unroll
    for (int c = 0; c < 4; c++) sum += v[c].x + v[c].y + v[c].z + v[c].w;
    float mean = wred_sum(sum) * (1.0f / H_);
    float ss = 0.f;
    #pragma unroll
    for (int c = 0; c < 4; c++) {
        float dx = v[c].x - mean, dy = v[c].y - mean, dz = v[c].z - mean, dw = v[c].w - mean;
        ss += dx * dx + dy * dy + dz * dz + dw * dw;
    }
    float var = wred_sum(ss) * (1.0f / H_);
    float rstd = rsqrtf(var + 1e-5f);
    float4* o = (float4*)(out + (size_t)m * H_);
    #pragma unroll
    for (int c = 0; c < 4; c++) {
        int q = lane + 32 * c;
        float4 gv = ((const float4*)lng)[q];
        float4 bv = ((const float4*)lnb)[q];
        float4 r;
        r.x = (v[c].x - mean) * rstd * gv.x + bv.x;
        r.y = (v[c].y - mean) * rstd * gv.y + bv.y;
        r.z = (v[c].z - mean) * rstd * gv.z + bv.z;
        r.w = (v[c].w - mean) * rstd * gv.w + bv.w;
        o[q] = r;
    }
}

// ---------------------------------------------------------------------------
// Launch
// ---------------------------------------------------------------------------
extern "C" void kernel_launch(void* const* d_in, const int* in_sizes, int n_in,
                              void* d_out, int out_size)
{
    const float* visual = (const float*)d_in[0];
    const float* audio  = (const float*)d_in[1];
    const float* in_W   = (const float*)d_in[2];
    const float* in_b   = (const float*)d_in[3];
    const float* out_W  = (const float*)d_in[4];
    const float* out_b  = (const float*)d_in[5];

    float *x, *sp, *P, *S, *C, *attn0, *cos0;
    cudaGetSymbolAddress((void**)&x, g_x);
    cudaGetSymbolAddress((void**)&sp, g_sp);
    cudaGetSymbolAddress((void**)&P, g_P);
    cudaGetSymbolAddress((void**)&S, g_S);
    cudaGetSymbolAddress((void**)&C, g_C);
    cudaGetSymbolAddress((void**)&attn0, g_attn0);
    cudaGetSymbolAddress((void**)&cos0, g_cos0);

    cudaFuncSetAttribute(attn_k, cudaFuncAttributeMaxDynamicSharedMemorySize, ATTN_SMEM);

    float* outp = (float*)d_out;

    dim3 gfull(4, (ROWS + 127) / 128);
    dim3 gtemp(4, (TROWS + 127) / 128);

    // input projection
    {
        int nthr = 256;
        int nblk = (ROWS * H4 + nthr - 1) / nthr;
        gather_k<<<nblk, nthr>>>(visual, audio, P);
        mmagemm_k<0><<<gfull, 256>>>(P, in_W, in_b, nullptr, x, ROWS);
    }

    for (int layer = 0; layer < 2; layer++) {
        const float* edge = (const float*)d_in[6 + 8 * layer];
        const float* lng  = (const float*)d_in[7 + 8 * layer];
        const float* lnb  = (const float*)d_in[8 + 8 * layer];
        const float* Wc   = (const float*)d_in[9 + 8 * layer];
        const float* bc   = (const float*)d_in[10 + 8 * layer];
        const float* Ws   = (const float*)d_in[11 + 8 * layer];
        const float* bs   = (const float*)d_in[12 + 8 * layer];
        const float* Wo   = (const float*)d_in[13 + 8 * layer];

        float* attn_out = (layer == 1) ? (outp + OUT_MAIN) : attn0;
        float* cos_out  = (layer == 1) ? (outp + OUT_MAIN + OUT_ATTN) : cos0;

        attn_k<<<FRAMES, 512, ATTN_SMEM>>>(x, edge, lng, lnb, sp, attn_out);

        {
            int nblk = (TROWS * 32 + 255) / 256;
            cos_k<<<nblk, 256>>>(sp, cos_out, P, S);
        }

        mmagemm_k<1><<<gtemp, 256>>>(P, Wc, bc, nullptr, C, TROWS);
        mmagemm_k<2><<<gtemp, 256>>>(S, Ws, bs, C, C, TROWS);

        {
            int nblk = (ROWS * 32 + 255) / 256;
            assemble_k<<<nblk, 256>>>(sp, C, lng, lnb, P);
        }

        mmagemm_k<3><<<gfull, 256>>>(P, Wo, nullptr, x, x, ROWS);
    }

    // output projection
    mmagemm_k<0><<<gfull, 256>>>(x, out_W, out_b, nullptr, outp, ROWS);

    (void)in_sizes; (void)n_in; (void)out_size;
}

// round 6
// speedup vs baseline: 2.0697x; 1.1405x over previous
#include <cuda_runtime.h>
#include <cuda_bf16.h>
#include <cstdint>
#include <math.h>

// ---------------------------------------------------------------------------
// Problem constants
// ---------------------------------------------------------------------------
#define B_ 16
#define T_ 64
#define NV 49
#define NN 50
#define H_ 512
#define H4 128            // H/4 (float4 units)
#define FRAMES (B_ * T_)                 // 1024
#define ROWS   (FRAMES * NN)             // 51200
#define TROWS  (B_ * (T_ - 1) * NN)      // 50400
#define NEGV   (-1.0e9f)

// Output layout: [out (ROWS*H)] [attn (FRAMES*NN*NN)] [cos (TROWS)]
#define OUT_MAIN ((size_t)ROWS * H_)
#define OUT_ATTN ((size_t)FRAMES * NN * NN)

// ---------------------------------------------------------------------------
// Scratch (device globals; no runtime allocation allowed)
// ---------------------------------------------------------------------------
__device__ float g_x[ROWS * H_];     // node features fp32
__device__ float g_sp[ROWS * H_];    // spatial (post LN+relu)
__device__ float g_C[ROWS * H_];     // tc, then tc+ts
__device__ __nv_bfloat16 g_phi[ROWS * H_];   // P hi
__device__ __nv_bfloat16 g_plo[ROWS * H_];   // P lo
__device__ __nv_bfloat16 g_shi[ROWS * H_];   // S hi
__device__ __nv_bfloat16 g_slo[ROWS * H_];   // S lo
__device__ __nv_bfloat16 g_xhi[ROWS * H_];   // x hi (mode-3 epilogue)
__device__ __nv_bfloat16 g_xlo[ROWS * H_];   // x lo
__device__ __nv_bfloat16 g_whi[8 * H_ * H_]; // 8 weight matrices hi
__device__ __nv_bfloat16 g_wlo[8 * H_ * H_]; // 8 weight matrices lo
__device__ float g_attn0[FRAMES * NN * NN];
__device__ float g_cos0[TROWS];

// ---------------------------------------------------------------------------
// Generic helpers
// ---------------------------------------------------------------------------
__device__ __forceinline__ float wred_sum(float v) {
    #pragma unroll
    for (int o = 16; o; o >>= 1) v += __shfl_xor_sync(0xffffffffu, v, o);
    return v;
}
__device__ __forceinline__ float wred_max(float v) {
    #pragma unroll
    for (int o = 16; o; o >>= 1) v = fmaxf(v, __shfl_xor_sync(0xffffffffu, v, o));
    return v;
}
__device__ __forceinline__ float dot4(float4 a, float4 b) {
    return a.x * b.x + a.y * b.y + a.z * b.z + a.w * b.w;
}
__device__ __forceinline__ bool window_allow(int i, int j) {
    int qr = i / 7, qc = i % 7;
    int kr = j / 7, kc = j % 7;
    int r0 = max(qr - 1, 0);
    int c0 = min(max(qc - 1, 0), 4);
    return (kr >= r0) && (kr <= r0 + 2) && (kc >= c0) && (kc <= c0 + 2) && (i != j);
}
__device__ __forceinline__ uint32_t smem_u32(const void* p) {
    uint32_t a;
    asm("{ .reg .u64 t; cvta.to.shared.u64 t, %1; cvt.u32.u64 %0, t; }" : "=r"(a) : "l"(p));
    return a;
}
__device__ __forceinline__ uint32_t pkbf(__nv_bfloat16 a, __nv_bfloat16 b) {
    return (uint32_t)__bfloat16_as_ushort(a) | ((uint32_t)__bfloat16_as_ushort(b) << 16);
}
// split float pair into hi/lo bf16 packed words
__device__ __forceinline__ void split2(float x, float y, uint32_t& h, uint32_t& l) {
    __nv_bfloat16 hx = __float2bfloat16_rn(x);
    __nv_bfloat16 hy = __float2bfloat16_rn(y);
    __nv_bfloat16 lx = __float2bfloat16_rn(x - __bfloat162float(hx));
    __nv_bfloat16 ly = __float2bfloat16_rn(y - __bfloat162float(hy));
    h = pkbf(hx, hy);
    l = pkbf(lx, ly);
}
__device__ __forceinline__ void split4(float4 v, uint2& h, uint2& l) {
    split2(v.x, v.y, h.x, l.x);
    split2(v.z, v.w, h.y, l.y);
}

// ---------------------------------------------------------------------------
// mma.sync / cp.async helpers (sm_80+ PTX; works on plain sm_103 target)
// ---------------------------------------------------------------------------
__device__ __forceinline__ void ldsm4(uint32_t r[4], uint32_t addr) {
    asm volatile("ldmatrix.sync.aligned.m8n8.x4.shared.b16 {%0,%1,%2,%3}, [%4];"
                 : "=r"(r[0]), "=r"(r[1]), "=r"(r[2]), "=r"(r[3]) : "r"(addr));
}
__device__ __forceinline__ void mma16816(float c[4], const uint32_t a[4],
                                         uint32_t b0, uint32_t b1) {
    asm volatile(
        "mma.sync.aligned.m16n8k16.row.col.f32.bf16.bf16.f32 "
        "{%0,%1,%2,%3}, {%4,%5,%6,%7}, {%8,%9}, {%0,%1,%2,%3};"
        : "+f"(c[0]), "+f"(c[1]), "+f"(c[2]), "+f"(c[3])
        : "r"(a[0]), "r"(a[1]), "r"(a[2]), "r"(a[3]), "r"(b0), "r"(b1));
}
__device__ __forceinline__ void cpa16(uint32_t dst, const void* src) {
    asm volatile("cp.async.ca.shared.global [%0], [%1], 16;"
                 :: "r"(dst), "l"(src) : "memory");
}
#define CP_COMMIT() asm volatile("cp.async.commit_group;" ::: "memory")
#define CP_WAIT1()  asm volatile("cp.async.wait_group 1;" ::: "memory")
#define CP_WAIT0()  asm volatile("cp.async.wait_group 0;" ::: "memory")

// ---------------------------------------------------------------------------
// Weight split: fp32 [512,512] -> hi/lo bf16
// ---------------------------------------------------------------------------
__global__ void __launch_bounds__(256) convw_k(
    const float* __restrict__ W, __nv_bfloat16* __restrict__ hi,
    __nv_bfloat16* __restrict__ lo)
{
    int idx = blockIdx.x * blockDim.x + threadIdx.x;   // float4 index
    if (idx >= (H_ * H_) / 4) return;
    float4 v = ((const float4*)W)[idx];
    uint2 h, l;
    split4(v, h, l);
    ((uint2*)hi)[idx] = h;
    ((uint2*)lo)[idx] = l;
}

// ---------------------------------------------------------------------------
// bf16x3 tensor GEMM: C[M,512] = epi(A[M,512] @ W[512,512]^T)
// A and W given pre-split as hi/lo bf16. Block 128x128, 256 thr, 8 warps 2x4.
// cp.async double-buffered smem, K-chunk 32, 16 chunks.
//   MODE 0: + bias | 1: relu(+bias) | 2: D1 + relu(+bias) | 3: D1 + relu(.)
//   WB: additionally emit hi/lo bf16 of the result
// ---------------------------------------------------------------------------
#define LSTR 40                    // bf16 elems per smem row (80 B)
#define GS_TILE (128 * LSTR * 2)   // 10240 B per part
#define GS_STAGE (4 * GS_TILE)     // 40960 B: Ah, Al, Bh, Bl
#define GS_SMEM (2 * GS_STAGE)     // 81920 B

template <int MODE, bool WB>
__global__ void __launch_bounds__(256, 2) mmagemm_k(
    const __nv_bfloat16* __restrict__ Ahi, const __nv_bfloat16* __restrict__ Alo,
    const __nv_bfloat16* __restrict__ Whi, const __nv_bfloat16* __restrict__ Wlo,
    const float* __restrict__ bias, const float* __restrict__ D1,
    float* __restrict__ C,
    __nv_bfloat16* __restrict__ Chi, __nv_bfloat16* __restrict__ Clo, int M)
{
    extern __shared__ char dynsm[];
    const uint32_t sb = smem_u32(dynsm);

    const int tid = threadIdx.x;
    const int lane = tid & 31, wid = tid >> 5;
    const int wm = wid >> 2, wn = wid & 3;
    const int m0 = blockIdx.y * 128, n0 = blockIdx.x * 128;

    float acc[4][4][4];
    #pragma unroll
    for (int a = 0; a < 4; a++)
        #pragma unroll
        for (int b = 0; b < 4; b++)
            #pragma unroll
            for (int c = 0; c < 4; c++) acc[a][b][c] = 0.f;

    // load mapping: thread covers half of one A row + half of one B row
    const int lrow = tid >> 1;
    const int lhalf = tid & 1;
    const int arow = min(m0 + lrow, M - 1);           // clamp (zero rows handled by M guard in epi)
    const __nv_bfloat16* ah = Ahi + (size_t)arow * 512 + lhalf * 16;
    const __nv_bfloat16* al = Alo + (size_t)arow * 512 + lhalf * 16;
    const __nv_bfloat16* bh = Whi + (size_t)(n0 + lrow) * 512 + lhalf * 16;
    const __nv_bfloat16* bl = Wlo + (size_t)(n0 + lrow) * 512 + lhalf * 16;
    const uint32_t st_byte = ((uint32_t)lrow * LSTR + (uint32_t)lhalf * 16) * 2;

    // ldmatrix per-lane offsets (bytes within a part)
    const uint32_t a_off =
        (((uint32_t)(wm * 64 + (((lane >> 3) & 1) << 3) + (lane & 7))) * LSTR +
         (((lane >> 4) & 1) << 3)) * 2;
    const uint32_t b_off =
        (((uint32_t)(wn * 32 + (((lane >> 4) & 1) << 3) + (lane & 7))) * LSTR +
         (((lane >> 3) & 1) << 3)) * 2;

    // issue one chunk's loads into a stage
    auto issue = [&](int ck, int s) {
        const uint32_t st = sb + (uint32_t)s * GS_STAGE + st_byte;
        const int off = ck * 32;
        cpa16(st + 0 * GS_TILE,       ah + off);
        cpa16(st + 0 * GS_TILE + 16,  ah + off + 8);
        cpa16(st + 1 * GS_TILE,       al + off);
        cpa16(st + 1 * GS_TILE + 16,  al + off + 8);
        cpa16(st + 2 * GS_TILE,       bh + off);
        cpa16(st + 2 * GS_TILE + 16,  bh + off + 8);
        cpa16(st + 3 * GS_TILE,       bl + off);
        cpa16(st + 3 * GS_TILE + 16,  bl + off + 8);
    };

    issue(0, 0); CP_COMMIT();
    issue(1, 1); CP_COMMIT();

    #pragma unroll 1
    for (int ck = 0; ck < 16; ck++) {
        if (ck < 15) { CP_WAIT1(); } else { CP_WAIT0(); }
        __syncthreads();

        const uint32_t base = sb + (uint32_t)(ck & 1) * GS_STAGE;
        #pragma unroll
        for (int ks = 0; ks < 2; ks++) {
            const uint32_t kb = (uint32_t)ks * 32;
            #pragma unroll
            for (int combo = 0; combo < 3; combo++) {
                const uint32_t apart = (combo == 2) ? GS_TILE : 0u;           // Al : Ah
                const uint32_t bpart = (combo == 1) ? 3u * GS_TILE : 2u * GS_TILE; // Bl : Bh
                uint32_t af[4][4], bfr[2][4];
                #pragma unroll
                for (int mt = 0; mt < 4; mt++)
                    ldsm4(af[mt], base + apart + a_off + (uint32_t)mt * (16 * LSTR * 2) + kb);
                #pragma unroll
                for (int p = 0; p < 2; p++)
                    ldsm4(bfr[p], base + bpart + b_off + (uint32_t)p * (16 * LSTR * 2) + kb);
                #pragma unroll
                for (int mt = 0; mt < 4; mt++)
                    #pragma unroll
                    for (int p = 0; p < 2; p++) {
                        mma16816(acc[mt][p * 2 + 0], af[mt], bfr[p][0], bfr[p][1]);
                        mma16816(acc[mt][p * 2 + 1], af[mt], bfr[p][2], bfr[p][3]);
                    }
            }
        }
        __syncthreads();
        if (ck + 2 < 16) { issue(ck + 2, ck & 1); CP_COMMIT(); }
    }

    // ------- epilogue -------
    const int r = lane >> 2;
    const int cc = (lane & 3) * 2;
    #pragma unroll
    for (int mt = 0; mt < 4; mt++) {
        #pragma unroll
        for (int nt = 0; nt < 4; nt++) {
            const int gm = m0 + wm * 64 + mt * 16 + r;
            const int gn = n0 + wn * 32 + nt * 8 + cc;
            float2 bb = make_float2(0.f, 0.f);
            if (MODE == 0 || MODE == 1 || MODE == 2) bb = *(const float2*)(bias + gn);
            #pragma unroll
            for (int h = 0; h < 2; h++) {
                const int gmr = gm + h * 8;
                if (gmr >= M) continue;
                float2 v = make_float2(acc[mt][nt][h * 2 + 0], acc[mt][nt][h * 2 + 1]);
                if (MODE == 0 || MODE == 1 || MODE == 2) { v.x += bb.x; v.y += bb.y; }
                if (MODE >= 1) { v.x = fmaxf(v.x, 0.f); v.y = fmaxf(v.y, 0.f); }
                if (MODE == 2 || MODE == 3) {
                    float2 d = *(const float2*)(D1 + (size_t)gmr * 512 + gn);
                    v.x += d.x; v.y += d.y;
                }
                *(float2*)(C + (size_t)gmr * 512 + gn) = v;
                if (WB) {
                    uint32_t hh, ll;
                    split2(v.x, v.y, hh, ll);
                    *(uint32_t*)(Chi + (size_t)gmr * 512 + gn) = hh;
                    *(uint32_t*)(Clo + (size_t)gmr * 512 + gn) = ll;
                }
            }
        }
    }
}

// ---------------------------------------------------------------------------
// Gather: concat(visual, audio) -> hi/lo bf16 [ROWS, H]
// ---------------------------------------------------------------------------
__global__ void __launch_bounds__(256) gather_k(
    const float* __restrict__ visual, const float* __restrict__ audio,
    __nv_bfloat16* __restrict__ ohi, __nv_bfloat16* __restrict__ olo)
{
    int idx = blockIdx.x * blockDim.x + threadIdx.x;
    if (idx >= ROWS * H4) return;
    int m = idx >> 7;
    int q = idx & 127;
    int i = m % NN;
    int bt = m / NN;
    float4 v;
    if (i < NV) {
        v = ((const float4*)visual)[((size_t)bt * NV + i) * H4 + q];
    } else {
        v = ((const float4*)audio)[(size_t)bt * H4 + q];
    }
    uint2 h, l;
    split4(v, h, l);
    ((uint2*)ohi)[idx] = h;
    ((uint2*)olo)[idx] = l;
}

// ---------------------------------------------------------------------------
// Per-frame attention + aggregation + residual + LN + relu
// ---------------------------------------------------------------------------
__global__ void __launch_bounds__(512) attn_k(
    const float* __restrict__ x, const float* __restrict__ edge,
    const float* __restrict__ lng, const float* __restrict__ lnb,
    float* __restrict__ spo, float* __restrict__ attn_out)
{
    extern __shared__ float sm[];
    float* xs   = sm;
    float* spb  = xs + NN * H_;
    float* es   = spb + NN * H_;
    float* Smat = es + 3 * H_;
    float* nx2  = Smat + NN * 52;
    float* d0   = nx2 + NN;
    float* d1   = d0 + NN;
    float* d2   = d1 + NN;
    float* rowsum = d2 + NN;
    float* ne   = rowsum + NN;

    const int tid = threadIdx.x;
    const int wid = tid >> 5, lane = tid & 31;
    const int f = blockIdx.x;

    float4* xs4 = (float4*)xs;
    float4* sp4 = (float4*)spb;
    float4* es4 = (float4*)es;
    const float4* xg = (const float4*)(x + (size_t)f * NN * H_);
    const float4* eg = (const float4*)edge;

    for (int i = tid; i < NN * H4; i += 512) xs4[i] = xg[i];
    for (int i = tid; i < 3 * H4; i += 512) es4[i] = eg[i];
    __syncthreads();

    for (int i = wid; i < NN + 3; i += 16) {
        if (i < NN) {
            float xx = 0.f, a0 = 0.f, a1 = 0.f, a2 = 0.f;
            for (int q = lane; q < H4; q += 32) {
                float4 xv = xs4[i * H4 + q];
                float4 e0v = es4[q], e1v = es4[H4 + q], e2v = es4[2 * H4 + q];
                xx += dot4(xv, xv);
                a0 += dot4(xv, e0v);
                a1 += dot4(xv, e1v);
                a2 += dot4(xv, e2v);
            }
            xx = wred_sum(xx); a0 = wred_sum(a0); a1 = wred_sum(a1); a2 = wred_sum(a2);
            if (lane == 0) { nx2[i] = xx; d0[i] = a0; d1[i] = a1; d2[i] = a2; }
        } else {
            int e = i - NN;
            float s = 0.f;
            for (int q = lane; q < H4; q += 32) { float4 ev = es4[e * H4 + q]; s += dot4(ev, ev); }
            s = wred_sum(s);
            if (lane == 0) ne[e] = s;
        }
    }
    __syncthreads();

    for (int idx = tid; idx < NN * NN; idx += 512) {
        int i = idx / NN, j = idx % NN;
        bool masked;
        if (i == j) masked = true;
        else if (i < NV && j < NV) masked = !window_allow(i, j);
        else masked = false;
        float v;
        if (masked) {
            v = NEGV;
        } else {
            float4 acc = make_float4(0.f, 0.f, 0.f, 0.f);
            const float4* xi = &xs4[i * H4];
            const float4* xj = &xs4[j * H4];
            #pragma unroll 4
            for (int q = 0; q < H4; q++) {
                float4 a = xi[q], b = xj[q];
                acc.x = fmaf(a.x, b.x, acc.x);
                acc.y = fmaf(a.y, b.y, acc.y);
                acc.z = fmaf(a.z, b.z, acc.z);
                acc.w = fmaf(a.w, b.w, acc.w);
            }
            float g = acc.x + acc.y + acc.z + acc.w;
            float num, qn2, kn2;
            if (i < NV && j < NV)      { num = g + d0[i];  qn2 = nx2[i];  kn2 = nx2[j]  + 2.f * d0[j]  + ne[0]; }
            else if (i == NV)          { num = g + d1[NV]; qn2 = nx2[NV]; kn2 = nx2[j]  + 2.f * d1[j]  + ne[1]; }
            else                       { num = g + d2[i];  qn2 = nx2[i];  kn2 = nx2[NV] + 2.f * d2[NV] + ne[2]; }
            v = num / (fmaxf(sqrtf(qn2), 1e-12f) * fmaxf(sqrtf(kn2), 1e-12f));
        }
        Smat[i * 52 + j] = v;
    }
    __syncthreads();

    for (int i = wid; i < NN; i += 16) {
        float v0 = (lane < NN) ? Smat[i * 52 + lane] : -3.0e38f;
        float v1 = (lane + 32 < NN) ? Smat[i * 52 + lane + 32] : -3.0e38f;
        float m = wred_max(fmaxf(v0, v1));
        float e0 = (lane < NN) ? expf(v0 - m) : 0.f;
        float e1 = (lane + 32 < NN) ? expf(v1 - m) : 0.f;
        float s = wred_sum(e0 + e1);
        float inv = 1.0f / s;
        float p0 = e0 * inv, p1 = e1 * inv;
        float rs = wred_sum(((lane < NV) ? p0 : 0.f) + ((lane + 32 < NV) ? p1 : 0.f));
        if (lane < NN) {
            Smat[i * 52 + lane] = p0;
            attn_out[(size_t)f * (NN * NN) + i * NN + lane] = p0;
        }
        if (lane + 32 < NN) {
            Smat[i * 52 + lane + 32] = p1;
            attn_out[(size_t)f * (NN * NN) + i * NN + lane + 32] = p1;
        }
        if (lane == 0) rowsum[i] = rs;
    }
    __syncthreads();

    for (int idx = tid; idx < NN * H4; idx += 512) {
        int i = idx >> 7, q = idx & 127;
        const float* Ar = &Smat[i * 52];
        float4 acc = make_float4(0.f, 0.f, 0.f, 0.f);
        #pragma unroll 7
        for (int j = 0; j < NV; j++) {
            float a = Ar[j];
            float4 xv = xs4[j * H4 + q];
            acc.x = fmaf(a, xv.x, acc.x);
            acc.y = fmaf(a, xv.y, acc.y);
            acc.z = fmaf(a, xv.z, acc.z);
            acc.w = fmaf(a, xv.w, acc.w);
        }
        int sel = (i < NV) ? 0 : 1;
        float rs = rowsum[i];
        float4 ev = es4[sel * H4 + q];
        acc.x = fmaf(rs, ev.x, acc.x); acc.y = fmaf(rs, ev.y, acc.y);
        acc.z = fmaf(rs, ev.z, acc.z); acc.w = fmaf(rs, ev.w, acc.w);
        float a49 = Ar[NV];
        float4 x49 = xs4[NV * H4 + q];
        float4 e2v = es4[2 * H4 + q];
        acc.x = fmaf(a49, x49.x + e2v.x, acc.x);
        acc.y = fmaf(a49, x49.y + e2v.y, acc.y);
        acc.z = fmaf(a49, x49.z + e2v.z, acc.z);
        acc.w = fmaf(a49, x49.w + e2v.w, acc.w);
        float4 xi = xs4[i * H4 + q];
        acc.x += xi.x; acc.y += xi.y; acc.z += xi.z; acc.w += xi.w;
        sp4[idx] = acc;
    }
    __syncthreads();

    for (int i = wid; i < NN; i += 16) {
        float4 v[4];
        #pragma unroll
        for (int c = 0; c < 4; c++) v[c] = sp4[i * H4 + lane + 32 * c];
        float s = 0.f;
        #pragma unroll
        for (int c = 0; c < 4; c++) s += v[c].x + v[c].y + v[c].z + v[c].w;
        float mean = wred_sum(s) * (1.0f / H_);
        float ss = 0.f;
        #pragma unroll
        for (int c = 0; c < 4; c++) {
            float dx = v[c].x - mean, dy = v[c].y - mean, dz = v[c].z - mean, dw = v[c].w - mean;
            ss += dx * dx + dy * dy + dz * dz + dw * dw;
        }
        float var = wred_sum(ss) * (1.0f / H_);
        float rstd = rsqrtf(var + 1e-5f);
        float4* og = (float4*)(spo + ((size_t)f * NN + i) * H_);
        #pragma unroll
        for (int c = 0; c < 4; c++) {
            int q = lane + 32 * c;
            float4 gv = ((const float4*)lng)[q];
            float4 bv = ((const float4*)lnb)[q];
            float4 o;
            o.x = fmaxf((v[c].x - mean) * rstd * gv.x + bv.x, 0.f);
            o.y = fmaxf((v[c].y - mean) * rstd * gv.y + bv.y, 0.f);
            o.z = fmaxf((v[c].z - mean) * rstd * gv.z + bv.z, 0.f);
            o.w = fmaxf((v[c].w - mean) * rstd * gv.w + bv.w, 0.f);
            og[q] = o;
        }
    }
}

#define ATTN_SMEM ((2 * NN * H_ + 3 * H_ + NN * 52 + 5 * NN + 3 + 1) * 4)

// ---------------------------------------------------------------------------
// cos + build P = cos*prev, S = (1-cos)*cur  as hi/lo bf16
// ---------------------------------------------------------------------------
__global__ void __launch_bounds__(256) cos_k(
    const float* __restrict__ sp, float* __restrict__ cosout,
    __nv_bfloat16* __restrict__ phi, __nv_bfloat16* __restrict__ plo,
    __nv_bfloat16* __restrict__ shi, __nv_bfloat16* __restrict__ slo)
{
    int gw = (blockIdx.x * blockDim.x + threadIdx.x) >> 5;
    int lane = threadIdx.x & 31;
    if (gw >= TROWS) return;
    int i = gw % NN;
    int bt = gw / NN;
    int b = bt / (T_ - 1);
    int tm1 = bt % (T_ - 1);
    const float4* cur  = (const float4*)(sp + ((size_t)(b * T_ + tm1 + 1) * NN + i) * H_);
    const float4* prev = (const float4*)(sp + ((size_t)(b * T_ + tm1) * NN + i) * H_);
    float dot = 0.f, na2 = 0.f, nb2 = 0.f;
    for (int q = lane; q < H4; q += 32) {
        float4 c = cur[q], p = prev[q];
        dot += dot4(c, p);
        na2 += dot4(c, c);
        nb2 += dot4(p, p);
    }
    dot = wred_sum(dot); na2 = wred_sum(na2); nb2 = wred_sum(nb2);
    float cosv = dot / (fmaxf(sqrtf(na2), 1e-8f) * fmaxf(sqrtf(nb2), 1e-8f));
    if (lane == 0) cosout[gw] = cosv;
    float omc = 1.0f - cosv;
    uint2* ph = (uint2*)phi + (size_t)gw * H4;
    uint2* pl = (uint2*)plo + (size_t)gw * H4;
    uint2* sh = (uint2*)shi + (size_t)gw * H4;
    uint2* sl = (uint2*)slo + (size_t)gw * H4;
    for (int q = lane; q < H4; q += 32) {
        float4 p = prev[q], c = cur[q];
        float4 pv = make_float4(cosv * p.x, cosv * p.y, cosv * p.z, cosv * p.w);
        float4 sv = make_float4(omc * c.x, omc * c.y, omc * c.z, omc * c.w);
        uint2 h, l;
        split4(pv, h, l); ph[q] = h; pl[q] = l;
        split4(sv, h, l); sh[q] = h; sl[q] = l;
    }
}

// ---------------------------------------------------------------------------
// assemble out_nodes + layernorm -> hi/lo bf16
// ---------------------------------------------------------------------------
__global__ void __launch_bounds__(256) assemble_k(
    const float* __restrict__ sp, const float* __restrict__ upd,
    const float* __restrict__ lng, const float* __restrict__ lnb,
    __nv_bfloat16* __restrict__ ohi, __nv_bfloat16* __restrict__ olo)
{
    int m = (blockIdx.x * blockDim.x + threadIdx.x) >> 5;
    int lane = threadIdx.x & 31;
    if (m >= ROWS) return;
    int i = m % NN;
    int t = (m / NN) % T_;
    int b = m / (NN * T_);
    const float4* s = (const float4*)(sp + (size_t)m * H_);
    float4 v[4];
    #pragma unroll
    for (int c = 0; c < 4; c++) v[c] = s[lane + 32 * c];
    if (t > 0) {
        size_t r = (size_t)(b * (T_ - 1) + (t - 1)) * NN + i;
        const float4* u = (const float4*)(upd + r * H_);
        #pragma unroll
        for (int c = 0; c < 4; c++) {
            float4 uu = u[lane + 32 * c];
            v[c].x += uu.x; v[c].y += uu.y; v[c].z += uu.z; v[c].w += uu.w;
        }
    }
    float sum = 0.f;
    #pragma unroll
    for (int c = 0; c < 4; c++) sum += v[c].x + v[c].y + v[c].z + v[c].w;
    float mean = wred_sum(sum) * (1.0f / H_);
    float ss = 0.f;
    #pragma unroll
    for (int c = 0; c < 4; c++) {
        float dx = v[c].x - mean, dy = v[c].y - mean, dz = v[c].z - mean, dw = v[c].w - mean;
        ss += dx * dx + dy * dy + dz * dz + dw * dw;
    }
    float var = wred_sum(ss) * (1.0f / H_);
    float rstd = rsqrtf(var + 1e-5f);
    uint2* oh = (uint2*)ohi + (size_t)m * H4;
    uint2* ol = (uint2*)olo + (size_t)m * H4;
    #pragma unroll
    for (int c = 0; c < 4; c++) {
        int q = lane + 32 * c;
        float4 gv = ((const float4*)lng)[q];
        float4 bv = ((const float4*)lnb)[q];
        float4 r;
        r.x = (v[c].x - mean) * rstd * gv.x + bv.x;
        r.y = (v[c].y - mean) * rstd * gv.y + bv.y;
        r.z = (v[c].z - mean) * rstd * gv.z + bv.z;
        r.w = (v[c].w - mean) * rstd * gv.w + bv.w;
        uint2 h, l;
        split4(r, h, l);
        oh[q] = h; ol[q] = l;
    }
}

// ---------------------------------------------------------------------------
// Launch
// ---------------------------------------------------------------------------
extern "C" void kernel_launch(void* const* d_in, const int* in_sizes, int n_in,
                              void* d_out, int out_size)
{
    const float* visual = (const float*)d_in[0];
    const float* audio  = (const float*)d_in[1];
    const float* in_W   = (const float*)d_in[2];
    const float* in_b   = (const float*)d_in[3];
    const float* out_W  = (const float*)d_in[4];
    const float* out_b  = (const float*)d_in[5];

    float *x, *sp, *C, *attn0, *cos0;
    __nv_bfloat16 *phi, *plo, *shi, *slo, *xhi, *xlo, *whi, *wlo;
    cudaGetSymbolAddress((void**)&x, g_x);
    cudaGetSymbolAddress((void**)&sp, g_sp);
    cudaGetSymbolAddress((void**)&C, g_C);
    cudaGetSymbolAddress((void**)&phi, g_phi);
    cudaGetSymbolAddress((void**)&plo, g_plo);
    cudaGetSymbolAddress((void**)&shi, g_shi);
    cudaGetSymbolAddress((void**)&slo, g_slo);
    cudaGetSymbolAddress((void**)&xhi, g_xhi);
    cudaGetSymbolAddress((void**)&xlo, g_xlo);
    cudaGetSymbolAddress((void**)&whi, g_whi);
    cudaGetSymbolAddress((void**)&wlo, g_wlo);
    cudaGetSymbolAddress((void**)&attn0, g_attn0);
    cudaGetSymbolAddress((void**)&cos0, g_cos0);

    cudaFuncSetAttribute(attn_k, cudaFuncAttributeMaxDynamicSharedMemorySize, ATTN_SMEM);
    cudaFuncSetAttribute((const void*)mmagemm_k<0, false>, cudaFuncAttributeMaxDynamicSharedMemorySize, GS_SMEM);
    cudaFuncSetAttribute((const void*)mmagemm_k<1, false>, cudaFuncAttributeMaxDynamicSharedMemorySize, GS_SMEM);
    cudaFuncSetAttribute((const void*)mmagemm_k<2, false>, cudaFuncAttributeMaxDynamicSharedMemorySize, GS_SMEM);
    cudaFuncSetAttribute((const void*)mmagemm_k<3, true>,  cudaFuncAttributeMaxDynamicSharedMemorySize, GS_SMEM);

    float* outp = (float*)d_out;

    dim3 gfull(4, (ROWS + 127) / 128);
    dim3 gtemp(4, (TROWS + 127) / 128);
    const int HH4 = (H_ * H_) / 4;

    // weight splits (W order: in, Wc0, Ws0, Wo0, Wc1, Ws1, Wo1, out)
    const float* wsrc[8] = {
        in_W, (const float*)d_in[9], (const float*)d_in[11], (const float*)d_in[13],
        (const float*)d_in[17], (const float*)d_in[19], (const float*)d_in[21], out_W };
    for (int w = 0; w < 8; w++)
        convw_k<<<(HH4 + 255) / 256, 256>>>(wsrc[w], whi + (size_t)w * H_ * H_,
                                            wlo + (size_t)w * H_ * H_);

    // input projection
    {
        int nblk = (ROWS * H4 + 255) / 256;
        gather_k<<<nblk, 256>>>(visual, audio, phi, plo);
        mmagemm_k<0, false><<<gfull, 256, GS_SMEM>>>(
            phi, plo, whi + 0 * (size_t)H_ * H_, wlo + 0 * (size_t)H_ * H_,
            in_b, nullptr, x, nullptr, nullptr, ROWS);
    }

    for (int layer = 0; layer < 2; layer++) {
        const float* edge = (const float*)d_in[6 + 8 * layer];
        const float* lng  = (const float*)d_in[7 + 8 * layer];
        const float* lnb  = (const float*)d_in[8 + 8 * layer];
        const float* bc   = (const float*)d_in[10 + 8 * layer];
        const float* bs   = (const float*)d_in[12 + 8 * layer];
        const size_t wofs = (size_t)(1 + 3 * layer) * H_ * H_;   // Wc
        const size_t wofs2 = wofs + (size_t)H_ * H_;             // Ws
        const size_t wofs3 = wofs2 + (size_t)H_ * H_;            // Wo

        float* attn_out = (layer == 1) ? (outp + OUT_MAIN) : attn0;
        float* cos_out  = (layer == 1) ? (outp + OUT_MAIN + OUT_ATTN) : cos0;

        attn_k<<<FRAMES, 512, ATTN_SMEM>>>(x, edge, lng, lnb, sp, attn_out);

        {
            int nblk = (TROWS * 32 + 255) / 256;
            cos_k<<<nblk, 256>>>(sp, cos_out, phi, plo, shi, slo);
        }

        mmagemm_k<1, false><<<gtemp, 256, GS_SMEM>>>(
            phi, plo, whi + wofs, wlo + wofs, bc, nullptr, C, nullptr, nullptr, TROWS);
        mmagemm_k<2, false><<<gtemp, 256, GS_SMEM>>>(
            shi, slo, whi + wofs2, wlo + wofs2, bs, C, C, nullptr, nullptr, TROWS);

        {
            int nblk = (ROWS * 32 + 255) / 256;
            assemble_k<<<nblk, 256>>>(sp, C, lng, lnb, phi, plo);
        }

        mmagemm_k<3, true><<<gfull, 256, GS_SMEM>>>(
            phi, plo, whi + wofs3, wlo + wofs3, nullptr, x, x, xhi, xlo, ROWS);
    }

    // output projection
    mmagemm_k<0, false><<<gfull, 256, GS_SMEM>>>(
        xhi, xlo, whi + 7 * (size_t)H_ * H_, wlo + 7 * (size_t)H_ * H_,
        out_b, nullptr, outp, nullptr, nullptr, ROWS);

    (void)in_sizes; (void)n_in; (void)out_size;
}

// round 7
// speedup vs baseline: 2.0709x; 1.0006x over previous
#include <cuda_runtime.h>
#include <cuda_bf16.h>
#include <cstdint>
#include <math.h>

// ---------------------------------------------------------------------------
// Problem constants
// ---------------------------------------------------------------------------
#define B_ 16
#define T_ 64
#define NV 49
#define NN 50
#define H_ 512
#define H4 128            // H/4 (float4 units)
#define FRAMES (B_ * T_)                 // 1024
#define ROWS   (FRAMES * NN)             // 51200
#define TROWS  (B_ * (T_ - 1) * NN)      // 50400
#define NEGV   (-1.0e9f)

// Output layout: [out (ROWS*H)] [attn (FRAMES*NN*NN)] [cos (TROWS)]
#define OUT_MAIN ((size_t)ROWS * H_)
#define OUT_ATTN ((size_t)FRAMES * NN * NN)

// ---------------------------------------------------------------------------
// Scratch (device globals; no runtime allocation allowed)
// ---------------------------------------------------------------------------
__device__ float g_x[ROWS * H_];     // node features fp32
__device__ float g_sp[ROWS * H_];    // spatial (post LN+relu)
__device__ float g_C[ROWS * H_];     // tc, then tc+ts
__device__ __nv_bfloat16 g_phi[ROWS * H_];   // P hi
__device__ __nv_bfloat16 g_plo[ROWS * H_];   // P lo
__device__ __nv_bfloat16 g_shi[ROWS * H_];   // S hi
__device__ __nv_bfloat16 g_slo[ROWS * H_];   // S lo
__device__ __nv_bfloat16 g_xhi[ROWS * H_];   // x hi (mode-3 epilogue)
__device__ __nv_bfloat16 g_xlo[ROWS * H_];   // x lo
__device__ __nv_bfloat16 g_whi[8 * H_ * H_]; // 8 weight matrices hi
__device__ __nv_bfloat16 g_wlo[8 * H_ * H_]; // 8 weight matrices lo
__device__ float g_attn0[FRAMES * NN * NN];
__device__ float g_cos0[TROWS];

// ---------------------------------------------------------------------------
// Generic helpers
// ---------------------------------------------------------------------------
__device__ __forceinline__ float wred_sum(float v) {
    #pragma unroll
    for (int o = 16; o; o >>= 1) v += __shfl_xor_sync(0xffffffffu, v, o);
    return v;
}
__device__ __forceinline__ float wred_max(float v) {
    #pragma unroll
    for (int o = 16; o; o >>= 1) v = fmaxf(v, __shfl_xor_sync(0xffffffffu, v, o));
    return v;
}
__device__ __forceinline__ float dot4(float4 a, float4 b) {
    return a.x * b.x + a.y * b.y + a.z * b.z + a.w * b.w;
}
__device__ __forceinline__ bool window_allow(int i, int j) {
    int qr = i / 7, qc = i % 7;
    int kr = j / 7, kc = j % 7;
    int r0 = max(qr - 1, 0);
    int c0 = min(max(qc - 1, 0), 4);
    return (kr >= r0) && (kr <= r0 + 2) && (kc >= c0) && (kc <= c0 + 2) && (i != j);
}
__device__ __forceinline__ uint32_t smem_u32(const void* p) {
    uint32_t a;
    asm("{ .reg .u64 t; cvta.to.shared.u64 t, %1; cvt.u32.u64 %0, t; }" : "=r"(a) : "l"(p));
    return a;
}
__device__ __forceinline__ uint32_t pkbf(__nv_bfloat16 a, __nv_bfloat16 b) {
    return (uint32_t)__bfloat16_as_ushort(a) | ((uint32_t)__bfloat16_as_ushort(b) << 16);
}
// split float pair into hi/lo bf16 packed words
__device__ __forceinline__ void split2(float x, float y, uint32_t& h, uint32_t& l) {
    __nv_bfloat16 hx = __float2bfloat16_rn(x);
    __nv_bfloat16 hy = __float2bfloat16_rn(y);
    __nv_bfloat16 lx = __float2bfloat16_rn(x - __bfloat162float(hx));
    __nv_bfloat16 ly = __float2bfloat16_rn(y - __bfloat162float(hy));
    h = pkbf(hx, hy);
    l = pkbf(lx, ly);
}
__device__ __forceinline__ void split4(float4 v, uint2& h, uint2& l) {
    split2(v.x, v.y, h.x, l.x);
    split2(v.z, v.w, h.y, l.y);
}

// ---------------------------------------------------------------------------
// mma.sync / cp.async helpers (sm_80+ PTX; works on plain sm_103 target)
// ---------------------------------------------------------------------------
__device__ __forceinline__ void ldsm4(uint32_t r[4], uint32_t addr) {
    asm volatile("ldmatrix.sync.aligned.m8n8.x4.shared.b16 {%0,%1,%2,%3}, [%4];"
                 : "=r"(r[0]), "=r"(r[1]), "=r"(r[2]), "=r"(r[3]) : "r"(addr));
}
__device__ __forceinline__ void mma16816(float c[4], const uint32_t a[4],
                                         uint32_t b0, uint32_t b1) {
    asm volatile(
        "mma.sync.aligned.m16n8k16.row.col.f32.bf16.bf16.f32 "
        "{%0,%1,%2,%3}, {%4,%5,%6,%7}, {%8,%9}, {%0,%1,%2,%3};"
        : "+f"(c[0]), "+f"(c[1]), "+f"(c[2]), "+f"(c[3])
        : "r"(a[0]), "r"(a[1]), "r"(a[2]), "r"(a[3]), "r"(b0), "r"(b1));
}
__device__ __forceinline__ void cpa16(uint32_t dst, const void* src) {
    asm volatile("cp.async.ca.shared.global [%0], [%1], 16;"
                 :: "r"(dst), "l"(src) : "memory");
}
#define CP_COMMIT() asm volatile("cp.async.commit_group;" ::: "memory")
#define CP_WAIT1()  asm volatile("cp.async.wait_group 1;" ::: "memory")
#define CP_WAIT0()  asm volatile("cp.async.wait_group 0;" ::: "memory")

// ---------------------------------------------------------------------------
// Weight split (all 8 matrices in one launch)
// ---------------------------------------------------------------------------
struct WPtrs { const float* p[8]; };

__global__ void __launch_bounds__(256) convw_k(
    WPtrs wp, __nv_bfloat16* __restrict__ hi, __nv_bfloat16* __restrict__ lo)
{
    const int HH4 = (H_ * H_) / 4;
    int gidx = blockIdx.x * blockDim.x + threadIdx.x;
    int w = gidx / HH4;
    int idx = gidx - w * HH4;
    if (w >= 8) return;
    float4 v = ((const float4*)wp.p[w])[idx];
    uint2 h, l;
    split4(v, h, l);
    ((uint2*)(hi + (size_t)w * H_ * H_))[idx] = h;
    ((uint2*)(lo + (size_t)w * H_ * H_))[idx] = l;
}

// ---------------------------------------------------------------------------
// bf16x3 tensor GEMM: C[M,512] = epi(A[M,512] @ W[512,512]^T)
// A, W pre-split hi/lo bf16. Block 128x128, 256 thr, 8 warps 2x4.
// cp.async double-buffered, K-chunk 32, 16 chunks. Fragment-reuse mainloop.
//   MODE 0: + bias | 1: relu(+bias) | 2: D1 + relu(+bias) | 3: D1 + relu(.)
//   WB: additionally emit hi/lo bf16 of the result
// ---------------------------------------------------------------------------
#define LSTR 40                    // bf16 elems per smem row (80 B)
#define GS_TILE (128 * LSTR * 2)   // 10240 B per part
#define GS_STAGE (4 * GS_TILE)     // 40960 B: Ah, Al, Bh, Bl
#define GS_SMEM (2 * GS_STAGE)     // 81920 B

template <int MODE, bool WB>
__global__ void __launch_bounds__(256, 2) mmagemm_k(
    const __nv_bfloat16* __restrict__ Ahi, const __nv_bfloat16* __restrict__ Alo,
    const __nv_bfloat16* __restrict__ Whi, const __nv_bfloat16* __restrict__ Wlo,
    const float* __restrict__ bias, const float* __restrict__ D1,
    float* __restrict__ C,
    __nv_bfloat16* __restrict__ Chi, __nv_bfloat16* __restrict__ Clo, int M)
{
    extern __shared__ char dynsm[];
    const uint32_t sb = smem_u32(dynsm);

    const int tid = threadIdx.x;
    const int lane = tid & 31, wid = tid >> 5;
    const int wm = wid >> 2, wn = wid & 3;
    const int m0 = blockIdx.y * 128, n0 = blockIdx.x * 128;

    float acc[4][4][4];
    #pragma unroll
    for (int a = 0; a < 4; a++)
        #pragma unroll
        for (int b = 0; b < 4; b++)
            #pragma unroll
            for (int c = 0; c < 4; c++) acc[a][b][c] = 0.f;

    // load mapping: thread covers half of one A row + half of one B row
    const int lrow = tid >> 1;
    const int lhalf = tid & 1;
    const int arow = min(m0 + lrow, M - 1);
    const __nv_bfloat16* ah = Ahi + (size_t)arow * 512 + lhalf * 16;
    const __nv_bfloat16* al = Alo + (size_t)arow * 512 + lhalf * 16;
    const __nv_bfloat16* bh = Whi + (size_t)(n0 + lrow) * 512 + lhalf * 16;
    const __nv_bfloat16* bl = Wlo + (size_t)(n0 + lrow) * 512 + lhalf * 16;
    const uint32_t st_byte = ((uint32_t)lrow * LSTR + (uint32_t)lhalf * 16) * 2;

    // ldmatrix per-lane offsets (bytes within a part)
    const uint32_t a_off =
        (((uint32_t)(wm * 64 + (((lane >> 3) & 1) << 3) + (lane & 7))) * LSTR +
         (((lane >> 4) & 1) << 3)) * 2;
    const uint32_t b_off =
        (((uint32_t)(wn * 32 + (((lane >> 4) & 1) << 3) + (lane & 7))) * LSTR +
         (((lane >> 3) & 1) << 3)) * 2;

    auto issue = [&](int ck, int s) {
        const uint32_t st = sb + (uint32_t)s * GS_STAGE + st_byte;
        const int off = ck * 32;
        cpa16(st + 0 * GS_TILE,       ah + off);
        cpa16(st + 0 * GS_TILE + 16,  ah + off + 8);
        cpa16(st + 1 * GS_TILE,       al + off);
        cpa16(st + 1 * GS_TILE + 16,  al + off + 8);
        cpa16(st + 2 * GS_TILE,       bh + off);
        cpa16(st + 2 * GS_TILE + 16,  bh + off + 8);
        cpa16(st + 3 * GS_TILE,       bl + off);
        cpa16(st + 3 * GS_TILE + 16,  bl + off + 8);
    };

    issue(0, 0); CP_COMMIT();
    issue(1, 1); CP_COMMIT();

    #pragma unroll 1
    for (int ck = 0; ck < 16; ck++) {
        if (ck < 15) { CP_WAIT1(); } else { CP_WAIT0(); }
        __syncthreads();

        const uint32_t base = sb + (uint32_t)(ck & 1) * GS_STAGE;
        #pragma unroll
        for (int ks = 0; ks < 2; ks++) {
            const uint32_t kb = (uint32_t)ks * 32;
            // hoist B fragments (hi + lo) once per ks
            uint32_t Bh[2][4], Bl[2][4];
            #pragma unroll
            for (int p = 0; p < 2; p++) {
                ldsm4(Bh[p], base + 2u * GS_TILE + b_off + (uint32_t)p * (16 * LSTR * 2) + kb);
                ldsm4(Bl[p], base + 3u * GS_TILE + b_off + (uint32_t)p * (16 * LSTR * 2) + kb);
            }
            #pragma unroll
            for (int mt = 0; mt < 4; mt++) {
                uint32_t Ah4[4], Al4[4];
                ldsm4(Ah4, base + a_off + (uint32_t)mt * (16 * LSTR * 2) + kb);
                ldsm4(Al4, base + GS_TILE + a_off + (uint32_t)mt * (16 * LSTR * 2) + kb);
                #pragma unroll
                for (int p = 0; p < 2; p++) {
                    mma16816(acc[mt][p * 2 + 0], Ah4, Bh[p][0], Bh[p][1]);
                    mma16816(acc[mt][p * 2 + 1], Ah4, Bh[p][2], Bh[p][3]);
                    mma16816(acc[mt][p * 2 + 0], Ah4, Bl[p][0], Bl[p][1]);
                    mma16816(acc[mt][p * 2 + 1], Ah4, Bl[p][2], Bl[p][3]);
                    mma16816(acc[mt][p * 2 + 0], Al4, Bh[p][0], Bh[p][1]);
                    mma16816(acc[mt][p * 2 + 1], Al4, Bh[p][2], Bh[p][3]);
                }
            }
        }
        __syncthreads();
        if (ck + 2 < 16) { issue(ck + 2, ck & 1); CP_COMMIT(); }
    }

    // ------- epilogue -------
    const int r = lane >> 2;
    const int cc = (lane & 3) * 2;
    #pragma unroll
    for (int mt = 0; mt < 4; mt++) {
        #pragma unroll
        for (int nt = 0; nt < 4; nt++) {
            const int gm = m0 + wm * 64 + mt * 16 + r;
            const int gn = n0 + wn * 32 + nt * 8 + cc;
            float2 bb = make_float2(0.f, 0.f);
            if (MODE == 0 || MODE == 1 || MODE == 2) bb = *(const float2*)(bias + gn);
            #pragma unroll
            for (int h = 0; h < 2; h++) {
                const int gmr = gm + h * 8;
                if (gmr >= M) continue;
                float2 v = make_float2(acc[mt][nt][h * 2 + 0], acc[mt][nt][h * 2 + 1]);
                if (MODE == 0 || MODE == 1 || MODE == 2) { v.x += bb.x; v.y += bb.y; }
                if (MODE >= 1) { v.x = fmaxf(v.x, 0.f); v.y = fmaxf(v.y, 0.f); }
                if (MODE == 2 || MODE == 3) {
                    float2 d = *(const float2*)(D1 + (size_t)gmr * 512 + gn);
                    v.x += d.x; v.y += d.y;
                }
                *(float2*)(C + (size_t)gmr * 512 + gn) = v;
                if (WB) {
                    uint32_t hh, ll;
                    split2(v.x, v.y, hh, ll);
                    *(uint32_t*)(Chi + (size_t)gmr * 512 + gn) = hh;
                    *(uint32_t*)(Clo + (size_t)gmr * 512 + gn) = ll;
                }
            }
        }
    }
}

// ---------------------------------------------------------------------------
// Gather: concat(visual, audio) -> hi/lo bf16 [ROWS, H]
// ---------------------------------------------------------------------------
__global__ void __launch_bounds__(256) gather_k(
    const float* __restrict__ visual, const float* __restrict__ audio,
    __nv_bfloat16* __restrict__ ohi, __nv_bfloat16* __restrict__ olo)
{
    int idx = blockIdx.x * blockDim.x + threadIdx.x;
    if (idx >= ROWS * H4) return;
    int m = idx >> 7;
    int q = idx & 127;
    int i = m % NN;
    int bt = m / NN;
    float4 v;
    if (i < NV) {
        v = ((const float4*)visual)[((size_t)bt * NV + i) * H4 + q];
    } else {
        v = ((const float4*)audio)[(size_t)bt * H4 + q];
    }
    uint2 h, l;
    split4(v, h, l);
    ((uint2*)ohi)[idx] = h;
    ((uint2*)olo)[idx] = l;
}

// ---------------------------------------------------------------------------
// Per-frame attention + aggregation + residual + LN + relu
// ---------------------------------------------------------------------------
__global__ void __launch_bounds__(512) attn_k(
    const float* __restrict__ x, const float* __restrict__ edge,
    const float* __restrict__ lng, const float* __restrict__ lnb,
    float* __restrict__ spo, float* __restrict__ attn_out)
{
    extern __shared__ float sm[];
    float* xs   = sm;
    float* spb  = xs + NN * H_;
    float* es   = spb + NN * H_;
    float* Smat = es + 3 * H_;
    float* nx2  = Smat + NN * 52;
    float* d0   = nx2 + NN;
    float* d1   = d0 + NN;
    float* d2   = d1 + NN;
    float* rowsum = d2 + NN;
    float* ne   = rowsum + NN;

    const int tid = threadIdx.x;
    const int wid = tid >> 5, lane = tid & 31;
    const int f = blockIdx.x;

    float4* xs4 = (float4*)xs;
    float4* sp4 = (float4*)spb;
    float4* es4 = (float4*)es;
    const float4* xg = (const float4*)(x + (size_t)f * NN * H_);
    const float4* eg = (const float4*)edge;

    for (int i = tid; i < NN * H4; i += 512) xs4[i] = xg[i];
    for (int i = tid; i < 3 * H4; i += 512) es4[i] = eg[i];
    __syncthreads();

    for (int i = wid; i < NN + 3; i += 16) {
        if (i < NN) {
            float xx = 0.f, a0 = 0.f, a1 = 0.f, a2 = 0.f;
            for (int q = lane; q < H4; q += 32) {
                float4 xv = xs4[i * H4 + q];
                float4 e0v = es4[q], e1v = es4[H4 + q], e2v = es4[2 * H4 + q];
                xx += dot4(xv, xv);
                a0 += dot4(xv, e0v);
                a1 += dot4(xv, e1v);
                a2 += dot4(xv, e2v);
            }
            xx = wred_sum(xx); a0 = wred_sum(a0); a1 = wred_sum(a1); a2 = wred_sum(a2);
            if (lane == 0) { nx2[i] = xx; d0[i] = a0; d1[i] = a1; d2[i] = a2; }
        } else {
            int e = i - NN;
            float s = 0.f;
            for (int q = lane; q < H4; q += 32) { float4 ev = es4[e * H4 + q]; s += dot4(ev, ev); }
            s = wred_sum(s);
            if (lane == 0) ne[e] = s;
        }
    }
    __syncthreads();

    for (int idx = tid; idx < NN * NN; idx += 512) {
        int i = idx / NN, j = idx % NN;
        bool masked;
        if (i == j) masked = true;
        else if (i < NV && j < NV) masked = !window_allow(i, j);
        else masked = false;
        float v;
        if (masked) {
            v = NEGV;
        } else {
            float4 acc = make_float4(0.f, 0.f, 0.f, 0.f);
            const float4* xi = &xs4[i * H4];
            const float4* xj = &xs4[j * H4];
            #pragma unroll 4
            for (int q = 0; q < H4; q++) {
                float4 a = xi[q], b = xj[q];
                acc.x = fmaf(a.x, b.x, acc.x);
                acc.y = fmaf(a.y, b.y, acc.y);
                acc.z = fmaf(a.z, b.z, acc.z);
                acc.w = fmaf(a.w, b.w, acc.w);
            }
            float g = acc.x + acc.y + acc.z + acc.w;
            float num, qn2, kn2;
            if (i < NV && j < NV)      { num = g + d0[i];  qn2 = nx2[i];  kn2 = nx2[j]  + 2.f * d0[j]  + ne[0]; }
            else if (i == NV)          { num = g + d1[NV]; qn2 = nx2[NV]; kn2 = nx2[j]  + 2.f * d1[j]  + ne[1]; }
            else                       { num = g + d2[i];  qn2 = nx2[i];  kn2 = nx2[NV] + 2.f * d2[NV] + ne[2]; }
            v = num / (fmaxf(sqrtf(qn2), 1e-12f) * fmaxf(sqrtf(kn2), 1e-12f));
        }
        Smat[i * 52 + j] = v;
    }
    __syncthreads();

    for (int i = wid; i < NN; i += 16) {
        float v0 = (lane < NN) ? Smat[i * 52 + lane] : -3.0e38f;
        float v1 = (lane + 32 < NN) ? Smat[i * 52 + lane + 32] : -3.0e38f;
        float m = wred_max(fmaxf(v0, v1));
        float e0 = (lane < NN) ? expf(v0 - m) : 0.f;
        float e1 = (lane + 32 < NN) ? expf(v1 - m) : 0.f;
        float s = wred_sum(e0 + e1);
        float inv = 1.0f / s;
        float p0 = e0 * inv, p1 = e1 * inv;
        float rs = wred_sum(((lane < NV) ? p0 : 0.f) + ((lane + 32 < NV) ? p1 : 0.f));
        if (lane < NN) {
            Smat[i * 52 + lane] = p0;
            attn_out[(size_t)f * (NN * NN) + i * NN + lane] = p0;
        }
        if (lane + 32 < NN) {
            Smat[i * 52 + lane + 32] = p1;
            attn_out[(size_t)f * (NN * NN) + i * NN + lane + 32] = p1;
        }
        if (lane == 0) rowsum[i] = rs;
    }
    __syncthreads();

    for (int idx = tid; idx < NN * H4; idx += 512) {
        int i = idx >> 7, q = idx & 127;
        const float* Ar = &Smat[i * 52];
        float4 acc = make_float4(0.f, 0.f, 0.f, 0.f);
        #pragma unroll 7
        for (int j = 0; j < NV; j++) {
            float a = Ar[j];
            float4 xv = xs4[j * H4 + q];
            acc.x = fmaf(a, xv.x, acc.x);
            acc.y = fmaf(a, xv.y, acc.y);
            acc.z = fmaf(a, xv.z, acc.z);
            acc.w = fmaf(a, xv.w, acc.w);
        }
        int sel = (i < NV) ? 0 : 1;
        float rs = rowsum[i];
        float4 ev = es4[sel * H4 + q];
        acc.x = fmaf(rs, ev.x, acc.x); acc.y = fmaf(rs, ev.y, acc.y);
        acc.z = fmaf(rs, ev.z, acc.z); acc.w = fmaf(rs, ev.w, acc.w);
        float a49 = Ar[NV];
        float4 x49 = xs4[NV * H4 + q];
        float4 e2v = es4[2 * H4 + q];
        acc.x = fmaf(a49, x49.x + e2v.x, acc.x);
        acc.y = fmaf(a49, x49.y + e2v.y, acc.y);
        acc.z = fmaf(a49, x49.z + e2v.z, acc.z);
        acc.w = fmaf(a49, x49.w + e2v.w, acc.w);
        float4 xi = xs4[i * H4 + q];
        acc.x += xi.x; acc.y += xi.y; acc.z += xi.z; acc.w += xi.w;
        sp4[idx] = acc;
    }
    __syncthreads();

    for (int i = wid; i < NN; i += 16) {
        float4 v[4];
        #pragma unroll
        for (int c = 0; c < 4; c++) v[c] = sp4[i * H4 + lane + 32 * c];
        float s = 0.f;
        #pragma unroll
        for (int c = 0; c < 4; c++) s += v[c].x + v[c].y + v[c].z + v[c].w;
        float mean = wred_sum(s) * (1.0f / H_);
        float ss = 0.f;
        #pragma unroll
        for (int c = 0; c < 4; c++) {
            float dx = v[c].x - mean, dy = v[c].y - mean, dz = v[c].z - mean, dw = v[c].w - mean;
            ss += dx * dx + dy * dy + dz * dz + dw * dw;
        }
        float var = wred_sum(ss) * (1.0f / H_);
        float rstd = rsqrtf(var + 1e-5f);
        float4* og = (float4*)(spo + ((size_t)f * NN + i) * H_);
        #pragma unroll
        for (int c = 0; c < 4; c++) {
            int q = lane + 32 * c;
            float4 gv = ((const float4*)lng)[q];
            float4 bv = ((const float4*)lnb)[q];
            float4 o;
            o.x = fmaxf((v[c].x - mean) * rstd * gv.x + bv.x, 0.f);
            o.y = fmaxf((v[c].y - mean) * rstd * gv.y + bv.y, 0.f);
            o.z = fmaxf((v[c].z - mean) * rstd * gv.z + bv.z, 0.f);
            o.w = fmaxf((v[c].w - mean) * rstd * gv.w + bv.w, 0.f);
            og[q] = o;
        }
    }
}

#define ATTN_SMEM ((2 * NN * H_ + 3 * H_ + NN * 52 + 5 * NN + 3 + 1) * 4)

// ---------------------------------------------------------------------------
// cos + build P = cos*prev, S = (1-cos)*cur  as hi/lo bf16
// ---------------------------------------------------------------------------
__global__ void __launch_bounds__(256) cos_k(
    const float* __restrict__ sp, float* __restrict__ cosout,
    __nv_bfloat16* __restrict__ phi, __nv_bfloat16* __restrict__ plo,
    __nv_bfloat16* __restrict__ shi, __nv_bfloat16* __restrict__ slo)
{
    int gw = (blockIdx.x * blockDim.x + threadIdx.x) >> 5;
    int lane = threadIdx.x & 31;
    if (gw >= TROWS) return;
    int i = gw % NN;
    int bt = gw / NN;
    int b = bt / (T_ - 1);
    int tm1 = bt % (T_ - 1);
    const float4* cur  = (const float4*)(sp + ((size_t)(b * T_ + tm1 + 1) * NN + i) * H_);
    const float4* prev = (const float4*)(sp + ((size_t)(b * T_ + tm1) * NN + i) * H_);
    float dot = 0.f, na2 = 0.f, nb2 = 0.f;
    for (int q = lane; q < H4; q += 32) {
        float4 c = cur[q], p = prev[q];
        dot += dot4(c, p);
        na2 += dot4(c, c);
        nb2 += dot4(p, p);
    }
    dot = wred_sum(dot); na2 = wred_sum(na2); nb2 = wred_sum(nb2);
    float cosv = dot / (fmaxf(sqrtf(na2), 1e-8f) * fmaxf(sqrtf(nb2), 1e-8f));
    if (lane == 0) cosout[gw] = cosv;
    float omc = 1.0f - cosv;
    uint2* ph = (uint2*)phi + (size_t)gw * H4;
    uint2* pl = (uint2*)plo + (size_t)gw * H4;
    uint2* sh = (uint2*)shi + (size_t)gw * H4;
    uint2* sl = (uint2*)slo + (size_t)gw * H4;
    for (int q = lane; q < H4; q += 32) {
        float4 p = prev[q], c = cur[q];
        float4 pv = make_float4(cosv * p.x, cosv * p.y, cosv * p.z, cosv * p.w);
        float4 sv = make_float4(omc * c.x, omc * c.y, omc * c.z, omc * c.w);
        uint2 h, l;
        split4(pv, h, l); ph[q] = h; pl[q] = l;
        split4(sv, h, l); sh[q] = h; sl[q] = l;
    }
}

// ---------------------------------------------------------------------------
// assemble out_nodes + layernorm -> hi/lo bf16
// ---------------------------------------------------------------------------
__global__ void __launch_bounds__(256) assemble_k(
    const float* __restrict__ sp, const float* __restrict__ upd,
    const float* __restrict__ lng, const float* __restrict__ lnb,
    __nv_bfloat16* __restrict__ ohi, __nv_bfloat16* __restrict__ olo)
{
    int m = (blockIdx.x * blockDim.x + threadIdx.x) >> 5;
    int lane = threadIdx.x & 31;
    if (m >= ROWS) return;
    int i = m % NN;
    int t = (m / NN) % T_;
    int b = m / (NN * T_);
    const float4* s = (const float4*)(sp + (size_t)m * H_);
    float4 v[4];
    #pragma unroll
    for (int c = 0; c < 4; c++) v[c] = s[lane + 32 * c];
    if (t > 0) {
        size_t r = (size_t)(b * (T_ - 1) + (t - 1)) * NN + i;
        const float4* u = (const float4*)(upd + r * H_);
        #pragma unroll
        for (int c = 0; c < 4; c++) {
            float4 uu = u[lane + 32 * c];
            v[c].x += uu.x; v[c].y += uu.y; v[c].z += uu.z; v[c].w += uu.w;
        }
    }
    float sum = 0.f;
    #pragma unroll
    for (int c = 0; c < 4; c++) sum += v[c].x + v[c].y + v[c].z + v[c].w;
    float mean = wred_sum(sum) * (1.0f / H_);
    float ss = 0.f;
    #pragma unroll
    for (int c = 0; c < 4; c++) {
        float dx = v[c].x - mean, dy = v[c].y - mean, dz = v[c].z - mean, dw = v[c].w - mean;
        ss += dx * dx + dy * dy + dz * dz + dw * dw;
    }
    float var = wred_sum(ss) * (1.0f / H_);
    float rstd = rsqrtf(var + 1e-5f);
    uint2* oh = (uint2*)ohi + (size_t)m * H4;
    uint2* ol = (uint2*)olo + (size_t)m * H4;
    #pragma unroll
    for (int c = 0; c < 4; c++) {
        int q = lane + 32 * c;
        float4 gv = ((const float4*)lng)[q];
        float4 bv = ((const float4*)lnb)[q];
        float4 r;
        r.x = (v[c].x - mean) * rstd * gv.x + bv.x;
        r.y = (v[c].y - mean) * rstd * gv.y + bv.y;
        r.z = (v[c].z - mean) * rstd * gv.z + bv.z;
        r.w = (v[c].w - mean) * rstd * gv.w + bv.w;
        uint2 h, l;
        split4(r, h, l);
        oh[q] = h; ol[q] = l;
    }
}

// ---------------------------------------------------------------------------
// Launch
// ---------------------------------------------------------------------------
extern "C" void kernel_launch(void* const* d_in, const int* in_sizes, int n_in,
                              void* d_out, int out_size)
{
    const float* visual = (const float*)d_in[0];
    const float* audio  = (const float*)d_in[1];
    const float* in_W   = (const float*)d_in[2];
    const float* in_b   = (const float*)d_in[3];
    const float* out_W  = (const float*)d_in[4];
    const float* out_b  = (const float*)d_in[5];

    float *x, *sp, *C, *attn0, *cos0;
    __nv_bfloat16 *phi, *plo, *shi, *slo, *xhi, *xlo, *whi, *wlo;
    cudaGetSymbolAddress((void**)&x, g_x);
    cudaGetSymbolAddress((void**)&sp, g_sp);
    cudaGetSymbolAddress((void**)&C, g_C);
    cudaGetSymbolAddress((void**)&phi, g_phi);
    cudaGetSymbolAddress((void**)&plo, g_plo);
    cudaGetSymbolAddress((void**)&shi, g_shi);
    cudaGetSymbolAddress((void**)&slo, g_slo);
    cudaGetSymbolAddress((void**)&xhi, g_xhi);
    cudaGetSymbolAddress((void**)&xlo, g_xlo);
    cudaGetSymbolAddress((void**)&whi, g_whi);
    cudaGetSymbolAddress((void**)&wlo, g_wlo);
    cudaGetSymbolAddress((void**)&attn0, g_attn0);
    cudaGetSymbolAddress((void**)&cos0, g_cos0);

    cudaFuncSetAttribute(attn_k, cudaFuncAttributeMaxDynamicSharedMemorySize, ATTN_SMEM);
    cudaFuncSetAttribute((const void*)mmagemm_k<0, false>, cudaFuncAttributeMaxDynamicSharedMemorySize, GS_SMEM);
    cudaFuncSetAttribute((const void*)mmagemm_k<1, false>, cudaFuncAttributeMaxDynamicSharedMemorySize, GS_SMEM);
    cudaFuncSetAttribute((const void*)mmagemm_k<2, false>, cudaFuncAttributeMaxDynamicSharedMemorySize, GS_SMEM);
    cudaFuncSetAttribute((const void*)mmagemm_k<3, true>,  cudaFuncAttributeMaxDynamicSharedMemorySize, GS_SMEM);

    float* outp = (float*)d_out;

    dim3 gfull(4, (ROWS + 127) / 128);
    dim3 gtemp(4, (TROWS + 127) / 128);
    const int HH4 = (H_ * H_) / 4;

    // weight splits (order: in, Wc0, Ws0, Wo0, Wc1, Ws1, Wo1, out) — one launch
    {
        WPtrs wp;
        wp.p[0] = in_W;
        wp.p[1] = (const float*)d_in[9];
        wp.p[2] = (const float*)d_in[11];
        wp.p[3] = (const float*)d_in[13];
        wp.p[4] = (const float*)d_in[17];
        wp.p[5] = (const float*)d_in[19];
        wp.p[6] = (const float*)d_in[21];
        wp.p[7] = out_W;
        convw_k<<<(8 * HH4 + 255) / 256, 256>>>(wp, whi, wlo);
    }

    // input projection
    {
        int nblk = (ROWS * H4 + 255) / 256;
        gather_k<<<nblk, 256>>>(visual, audio, phi, plo);
        mmagemm_k<0, false><<<gfull, 256, GS_SMEM>>>(
            phi, plo, whi + 0 * (size_t)H_ * H_, wlo + 0 * (size_t)H_ * H_,
            in_b, nullptr, x, nullptr, nullptr, ROWS);
    }

    for (int layer = 0; layer < 2; layer++) {
        const float* edge = (const float*)d_in[6 + 8 * layer];
        const float* lng  = (const float*)d_in[7 + 8 * layer];
        const float* lnb  = (const float*)d_in[8 + 8 * layer];
        const float* bc   = (const float*)d_in[10 + 8 * layer];
        const float* bs   = (const float*)d_in[12 + 8 * layer];
        const size_t wofs = (size_t)(1 + 3 * layer) * H_ * H_;   // Wc
        const size_t wofs2 = wofs + (size_t)H_ * H_;             // Ws
        const size_t wofs3 = wofs2 + (size_t)H_ * H_;            // Wo

        float* attn_out = (layer == 1) ? (outp + OUT_MAIN) : attn0;
        float* cos_out  = (layer == 1) ? (outp + OUT_MAIN + OUT_ATTN) : cos0;

        attn_k<<<FRAMES, 512, ATTN_SMEM>>>(x, edge, lng, lnb, sp, attn_out);

        {
            int nblk = (TROWS * 32 + 255) / 256;
            cos_k<<<nblk, 256>>>(sp, cos_out, phi, plo, shi, slo);
        }

        mmagemm_k<1, false><<<gtemp, 256, GS_SMEM>>>(
            phi, plo, whi + wofs, wlo + wofs, bc, nullptr, C, nullptr, nullptr, TROWS);
        mmagemm_k<2, false><<<gtemp, 256, GS_SMEM>>>(
            shi, slo, whi + wofs2, wlo + wofs2, bs, C, C, nullptr, nullptr, TROWS);

        {
            int nblk = (ROWS * 32 + 255) / 256;
            assemble_k<<<nblk, 256>>>(sp, C, lng, lnb, phi, plo);
        }

        mmagemm_k<3, true><<<gfull, 256, GS_SMEM>>>(
            phi, plo, whi + wofs3, wlo + wofs3, nullptr, x, x, xhi, xlo, ROWS);
    }

    // output projection
    mmagemm_k<0, false><<<gfull, 256, GS_SMEM>>>(
        xhi, xlo, whi + 7 * (size_t)H_ * H_, wlo + 7 * (size_t)H_ * H_,
        out_b, nullptr, outp, nullptr, nullptr, ROWS);

    (void)in_sizes; (void)n_in; (void)out_size;
}

// round 13
// speedup vs baseline: 2.0710x; 1.0000x over previous
#include <cuda_runtime.h>
#include <cuda_bf16.h>
#include <cstdint>
#include <math.h>

// ---------------------------------------------------------------------------
// Problem constants
// ---------------------------------------------------------------------------
#define B_ 16
#define T_ 64
#define NV 49
#define NN 50
#define H_ 512
#define H4 128            // H/4 (float4 units)
#define FRAMES (B_ * T_)                 // 1024
#define ROWS   (FRAMES * NN)             // 51200
#define TROWS  (B_ * (T_ - 1) * NN)      // 50400
#define NEGV   (-1.0e9f)

// Output layout: [out (ROWS*H)] [attn (FRAMES*NN*NN)] [cos (TROWS)]
#define OUT_MAIN ((size_t)ROWS * H_)
#define OUT_ATTN ((size_t)FRAMES * NN * NN)

// ---------------------------------------------------------------------------
// Scratch (device globals; no runtime allocation allowed)
// ---------------------------------------------------------------------------
__device__ float g_x[ROWS * H_];     // node features fp32
__device__ float g_sp[ROWS * H_];    // spatial (post LN+relu)
__device__ float g_C[ROWS * H_];     // tc, then tc+ts
__device__ __nv_bfloat16 g_phi[ROWS * H_];   // P hi
__device__ __nv_bfloat16 g_plo[ROWS * H_];   // P lo
__device__ __nv_bfloat16 g_shi[ROWS * H_];   // S hi
__device__ __nv_bfloat16 g_slo[ROWS * H_];   // S lo
__device__ __nv_bfloat16 g_xhi[ROWS * H_];   // x hi (mode-3 epilogue)
__device__ __nv_bfloat16 g_xlo[ROWS * H_];   // x lo
__device__ __nv_bfloat16 g_whi[8 * H_ * H_]; // 8 weight matrices hi
__device__ __nv_bfloat16 g_wlo[8 * H_ * H_]; // 8 weight matrices lo
__device__ float g_attn0[FRAMES * NN * NN];
__device__ float g_cos0[TROWS];

// ---------------------------------------------------------------------------
// Generic helpers
// ---------------------------------------------------------------------------
__device__ __forceinline__ float wred_sum(float v) {
    #pragma unroll
    for (int o = 16; o; o >>= 1) v += __shfl_xor_sync(0xffffffffu, v, o);
    return v;
}
__device__ __forceinline__ float wred_max(float v) {
    #pragma unroll
    for (int o = 16; o; o >>= 1) v = fmaxf(v, __shfl_xor_sync(0xffffffffu, v, o));
    return v;
}
__device__ __forceinline__ float dot4(float4 a, float4 b) {
    return a.x * b.x + a.y * b.y + a.z * b.z + a.w * b.w;
}
__device__ __forceinline__ bool window_allow(int i, int j) {
    int qr = i / 7, qc = i % 7;
    int kr = j / 7, kc = j % 7;
    int r0 = max(qr - 1, 0);
    int c0 = min(max(qc - 1, 0), 4);
    return (kr >= r0) && (kr <= r0 + 2) && (kc >= c0) && (kc <= c0 + 2) && (i != j);
}
__device__ __forceinline__ uint32_t smem_u32(const void* p) {
    uint32_t a;
    asm("{ .reg .u64 t; cvta.to.shared.u64 t, %1; cvt.u32.u64 %0, t; }" : "=r"(a) : "l"(p));
    return a;
}
__device__ __forceinline__ uint32_t pkbf(__nv_bfloat16 a, __nv_bfloat16 b) {
    return (uint32_t)__bfloat16_as_ushort(a) | ((uint32_t)__bfloat16_as_ushort(b) << 16);
}
// split float pair into hi/lo bf16 packed words
__device__ __forceinline__ void split2(float x, float y, uint32_t& h, uint32_t& l) {
    __nv_bfloat16 hx = __float2bfloat16_rn(x);
    __nv_bfloat16 hy = __float2bfloat16_rn(y);
    __nv_bfloat16 lx = __float2bfloat16_rn(x - __bfloat162float(hx));
    __nv_bfloat16 ly = __float2bfloat16_rn(y - __bfloat162float(hy));
    h = pkbf(hx, hy);
    l = pkbf(lx, ly);
}
__device__ __forceinline__ void split4(float4 v, uint2& h, uint2& l) {
    split2(v.x, v.y, h.x, l.x);
    split2(v.z, v.w, h.y, l.y);
}

// ---------------------------------------------------------------------------
// mma.sync / cp.async helpers (sm_80+ PTX; works on plain sm_103 target)
// ---------------------------------------------------------------------------
__device__ __forceinline__ void ldsm4(uint32_t r[4], uint32_t addr) {
    asm volatile("ldmatrix.sync.aligned.m8n8.x4.shared.b16 {%0,%1,%2,%3}, [%4];"
                 : "=r"(r[0]), "=r"(r[1]), "=r"(r[2]), "=r"(r[3]) : "r"(addr));
}
__device__ __forceinline__ void mma16816(float c[4], const uint32_t a[4],
                                         uint32_t b0, uint32_t b1) {
    asm volatile(
        "mma.sync.aligned.m16n8k16.row.col.f32.bf16.bf16.f32 "
        "{%0,%1,%2,%3}, {%4,%5,%6,%7}, {%8,%9}, {%0,%1,%2,%3};"
        : "+f"(c[0]), "+f"(c[1]), "+f"(c[2]), "+f"(c[3])
        : "r"(a[0]), "r"(a[1]), "r"(a[2]), "r"(a[3]), "r"(b0), "r"(b1));
}
__device__ __forceinline__ void cpa16(uint32_t dst, const void* src) {
    asm volatile("cp.async.ca.shared.global [%0], [%1], 16;"
                 :: "r"(dst), "l"(src) : "memory");
}
#define CP_COMMIT() asm volatile("cp.async.commit_group;" ::: "memory")
#define CP_WAIT1()  asm volatile("cp.async.wait_group 1;" ::: "memory")
#define CP_WAIT0()  asm volatile("cp.async.wait_group 0;" ::: "memory")

// ---------------------------------------------------------------------------
// Weight split (all 8 matrices in one launch)
// ---------------------------------------------------------------------------
struct WPtrs { const float* p[8]; };

__global__ void __launch_bounds__(256) convw_k(
    WPtrs wp, __nv_bfloat16* __restrict__ hi, __nv_bfloat16* __restrict__ lo)
{
    const int HH4 = (H_ * H_) / 4;
    int gidx = blockIdx.x * blockDim.x + threadIdx.x;
    int w = gidx / HH4;
    int idx = gidx - w * HH4;
    if (w >= 8) return;
    float4 v = ((const float4*)wp.p[w])[idx];
    uint2 h, l;
    split4(v, h, l);
    ((uint2*)(hi + (size_t)w * H_ * H_))[idx] = h;
    ((uint2*)(lo + (size_t)w * H_ * H_))[idx] = l;
}

// ---------------------------------------------------------------------------
// bf16x3 tensor GEMM (unchanged from R6)
// ---------------------------------------------------------------------------
#define LSTR 40                    // bf16 elems per smem row (80 B)
#define GS_TILE (128 * LSTR * 2)   // 10240 B per part
#define GS_STAGE (4 * GS_TILE)     // 40960 B: Ah, Al, Bh, Bl
#define GS_SMEM (2 * GS_STAGE)     // 81920 B

template <int MODE, bool WB>
__global__ void __launch_bounds__(256, 2) mmagemm_k(
    const __nv_bfloat16* __restrict__ Ahi, const __nv_bfloat16* __restrict__ Alo,
    const __nv_bfloat16* __restrict__ Whi, const __nv_bfloat16* __restrict__ Wlo,
    const float* __restrict__ bias, const float* __restrict__ D1,
    float* __restrict__ C,
    __nv_bfloat16* __restrict__ Chi, __nv_bfloat16* __restrict__ Clo, int M)
{
    extern __shared__ char dynsm[];
    const uint32_t sb = smem_u32(dynsm);

    const int tid = threadIdx.x;
    const int lane = tid & 31, wid = tid >> 5;
    const int wm = wid >> 2, wn = wid & 3;
    const int m0 = blockIdx.y * 128, n0 = blockIdx.x * 128;

    float acc[4][4][4];
    #pragma unroll
    for (int a = 0; a < 4; a++)
        #pragma unroll
        for (int b = 0; b < 4; b++)
            #pragma unroll
            for (int c = 0; c < 4; c++) acc[a][b][c] = 0.f;

    const int lrow = tid >> 1;
    const int lhalf = tid & 1;
    const int arow = min(m0 + lrow, M - 1);
    const __nv_bfloat16* ah = Ahi + (size_t)arow * 512 + lhalf * 16;
    const __nv_bfloat16* al = Alo + (size_t)arow * 512 + lhalf * 16;
    const __nv_bfloat16* bh = Whi + (size_t)(n0 + lrow) * 512 + lhalf * 16;
    const __nv_bfloat16* bl = Wlo + (size_t)(n0 + lrow) * 512 + lhalf * 16;
    const uint32_t st_byte = ((uint32_t)lrow * LSTR + (uint32_t)lhalf * 16) * 2;

    const uint32_t a_off =
        (((uint32_t)(wm * 64 + (((lane >> 3) & 1) << 3) + (lane & 7))) * LSTR +
         (((lane >> 4) & 1) << 3)) * 2;
    const uint32_t b_off =
        (((uint32_t)(wn * 32 + (((lane >> 4) & 1) << 3) + (lane & 7))) * LSTR +
         (((lane >> 3) & 1) << 3)) * 2;

    auto issue = [&](int ck, int s) {
        const uint32_t st = sb + (uint32_t)s * GS_STAGE + st_byte;
        const int off = ck * 32;
        cpa16(st + 0 * GS_TILE,       ah + off);
        cpa16(st + 0 * GS_TILE + 16,  ah + off + 8);
        cpa16(st + 1 * GS_TILE,       al + off);
        cpa16(st + 1 * GS_TILE + 16,  al + off + 8);
        cpa16(st + 2 * GS_TILE,       bh + off);
        cpa16(st + 2 * GS_TILE + 16,  bh + off + 8);
        cpa16(st + 3 * GS_TILE,       bl + off);
        cpa16(st + 3 * GS_TILE + 16,  bl + off + 8);
    };

    issue(0, 0); CP_COMMIT();
    issue(1, 1); CP_COMMIT();

    #pragma unroll 1
    for (int ck = 0; ck < 16; ck++) {
        if (ck < 15) { CP_WAIT1(); } else { CP_WAIT0(); }
        __syncthreads();

        const uint32_t base = sb + (uint32_t)(ck & 1) * GS_STAGE;
        #pragma unroll
        for (int ks = 0; ks < 2; ks++) {
            const uint32_t kb = (uint32_t)ks * 32;
            uint32_t Bh[2][4], Bl[2][4];
            #pragma unroll
            for (int p = 0; p < 2; p++) {
                ldsm4(Bh[p], base + 2u * GS_TILE + b_off + (uint32_t)p * (16 * LSTR * 2) + kb);
                ldsm4(Bl[p], base + 3u * GS_TILE + b_off + (uint32_t)p * (16 * LSTR * 2) + kb);
            }
            #pragma unroll
            for (int mt = 0; mt < 4; mt++) {
                uint32_t Ah4[4], Al4[4];
                ldsm4(Ah4, base + a_off + (uint32_t)mt * (16 * LSTR * 2) + kb);
                ldsm4(Al4, base + GS_TILE + a_off + (uint32_t)mt * (16 * LSTR * 2) + kb);
                #pragma unroll
                for (int p = 0; p < 2; p++) {
                    mma16816(acc[mt][p * 2 + 0], Ah4, Bh[p][0], Bh[p][1]);
                    mma16816(acc[mt][p * 2 + 1], Ah4, Bh[p][2], Bh[p][3]);
                    mma16816(acc[mt][p * 2 + 0], Ah4, Bl[p][0], Bl[p][1]);
                    mma16816(acc[mt][p * 2 + 1], Ah4, Bl[p][2], Bl[p][3]);
                    mma16816(acc[mt][p * 2 + 0], Al4, Bh[p][0], Bh[p][1]);
                    mma16816(acc[mt][p * 2 + 1], Al4, Bh[p][2], Bh[p][3]);
                }
            }
        }
        __syncthreads();
        if (ck + 2 < 16) { issue(ck + 2, ck & 1); CP_COMMIT(); }
    }

    const int r = lane >> 2;
    const int cc = (lane & 3) * 2;
    #pragma unroll
    for (int mt = 0; mt < 4; mt++) {
        #pragma unroll
        for (int nt = 0; nt < 4; nt++) {
            const int gm = m0 + wm * 64 + mt * 16 + r;
            const int gn = n0 + wn * 32 + nt * 8 + cc;
            float2 bb = make_float2(0.f, 0.f);
            if (MODE == 0 || MODE == 1 || MODE == 2) bb = *(const float2*)(bias + gn);
            #pragma unroll
            for (int h = 0; h < 2; h++) {
                const int gmr = gm + h * 8;
                if (gmr >= M) continue;
                float2 v = make_float2(acc[mt][nt][h * 2 + 0], acc[mt][nt][h * 2 + 1]);
                if (MODE == 0 || MODE == 1 || MODE == 2) { v.x += bb.x; v.y += bb.y; }
                if (MODE >= 1) { v.x = fmaxf(v.x, 0.f); v.y = fmaxf(v.y, 0.f); }
                if (MODE == 2 || MODE == 3) {
                    float2 d = *(const float2*)(D1 + (size_t)gmr * 512 + gn);
                    v.x += d.x; v.y += d.y;
                }
                *(float2*)(C + (size_t)gmr * 512 + gn) = v;
                if (WB) {
                    uint32_t hh, ll;
                    split2(v.x, v.y, hh, ll);
                    *(uint32_t*)(Chi + (size_t)gmr * 512 + gn) = hh;
                    *(uint32_t*)(Clo + (size_t)gmr * 512 + gn) = ll;
                }
            }
        }
    }
}

// ---------------------------------------------------------------------------
// Gather: concat(visual, audio) -> hi/lo bf16 [ROWS, H]
// ---------------------------------------------------------------------------
__global__ void __launch_bounds__(256) gather_k(
    const float* __restrict__ visual, const float* __restrict__ audio,
    __nv_bfloat16* __restrict__ ohi, __nv_bfloat16* __restrict__ olo)
{
    int idx = blockIdx.x * blockDim.x + threadIdx.x;
    if (idx >= ROWS * H4) return;
    int m = idx >> 7;
    int q = idx & 127;
    int i = m % NN;
    int bt = m / NN;
    float4 v;
    if (i < NV) {
        v = ((const float4*)visual)[((size_t)bt * NV + i) * H4 + q];
    } else {
        v = ((const float4*)audio)[(size_t)bt * H4 + q];
    }
    uint2 h, l;
    split4(v, h, l);
    ((uint2*)ohi)[idx] = h;
    ((uint2*)olo)[idx] = l;
}

// ---------------------------------------------------------------------------
// Per-frame attention: scores WARP-PER-PAIR (bank-conflict free)
// ---------------------------------------------------------------------------
__global__ void __launch_bounds__(512) attn_k(
    const float* __restrict__ x, const float* __restrict__ edge,
    const float* __restrict__ lng, const float* __restrict__ lnb,
    float* __restrict__ spo, float* __restrict__ attn_out)
{
    extern __shared__ float sm[];
    float* xs   = sm;
    float* spb  = xs + NN * H_;
    float* es   = spb + NN * H_;
    float* Smat = es + 3 * H_;
    float* nx2  = Smat + NN * 52;
    float* d0   = nx2 + NN;
    float* d1   = d0 + NN;
    float* d2   = d1 + NN;
    float* rowsum = d2 + NN;
    float* ne   = rowsum + NN;

    const int tid = threadIdx.x;
    const int wid = tid >> 5, lane = tid & 31;
    const int f = blockIdx.x;

    float4* xs4 = (float4*)xs;
    float4* sp4 = (float4*)spb;
    float4* es4 = (float4*)es;
    const float4* xg = (const float4*)(x + (size_t)f * NN * H_);
    const float4* eg = (const float4*)edge;

    for (int i = tid; i < NN * H4; i += 512) xs4[i] = xg[i];
    for (int i = tid; i < 3 * H4; i += 512) es4[i] = eg[i];
    __syncthreads();

    // per-row dots: |x_i|^2, x_i.e0, x_i.e1, x_i.e2  (+ edge norms)
    for (int i = wid; i < NN + 3; i += 16) {
        if (i < NN) {
            float xx = 0.f, a0 = 0.f, a1 = 0.f, a2 = 0.f;
            for (int q = lane; q < H4; q += 32) {
                float4 xv = xs4[i * H4 + q];
                float4 e0v = es4[q], e1v = es4[H4 + q], e2v = es4[2 * H4 + q];
                xx += dot4(xv, xv);
                a0 += dot4(xv, e0v);
                a1 += dot4(xv, e1v);
                a2 += dot4(xv, e2v);
            }
            xx = wred_sum(xx); a0 = wred_sum(a0); a1 = wred_sum(a1); a2 = wred_sum(a2);
            if (lane == 0) { nx2[i] = xx; d0[i] = a0; d1[i] = a1; d2[i] = a2; }
        } else {
            int e = i - NN;
            float s = 0.f;
            for (int q = lane; q < H4; q += 32) { float4 ev = es4[e * H4 + q]; s += dot4(ev, ev); }
            s = wred_sum(s);
            if (lane == 0) ne[e] = s;
        }
    }
    __syncthreads();

    // scores: one WARP per (i,j) pair; lanes split hidden dim (conflict-free)
    for (int p = wid; p < NN * NN; p += 16) {
        const int i = p / NN, j = p - i * NN;
        bool masked;
        if (i == j) masked = true;
        else if (i < NV && j < NV) masked = !window_allow(i, j);
        else masked = false;
        float v = NEGV;
        if (!masked) {
            const float4* xi = &xs4[i * H4];
            const float4* xj = &xs4[j * H4];
            float4 acc = make_float4(0.f, 0.f, 0.f, 0.f);
            #pragma unroll
            for (int c = 0; c < 4; c++) {
                const int q = lane + 32 * c;
                float4 a = xi[q], b = xj[q];
                acc.x = fmaf(a.x, b.x, acc.x);
                acc.y = fmaf(a.y, b.y, acc.y);
                acc.z = fmaf(a.z, b.z, acc.z);
                acc.w = fmaf(a.w, b.w, acc.w);
            }
            float g = wred_sum(acc.x + acc.y + acc.z + acc.w);
            float num, qn2, kn2;
            if (i < NV && j < NV)      { num = g + d0[i];  qn2 = nx2[i];  kn2 = nx2[j]  + 2.f * d0[j]  + ne[0]; }
            else if (i == NV)          { num = g + d1[NV]; qn2 = nx2[NV]; kn2 = nx2[j]  + 2.f * d1[j]  + ne[1]; }
            else                       { num = g + d2[i];  qn2 = nx2[i];  kn2 = nx2[NV] + 2.f * d2[NV] + ne[2]; }
            v = num / (fmaxf(sqrtf(qn2), 1e-12f) * fmaxf(sqrtf(kn2), 1e-12f));
        }
        if (lane == 0) Smat[i * 52 + j] = v;
    }
    __syncthreads();

    // softmax per row (warp per row) + write attn + rowsum over j<49
    for (int i = wid; i < NN; i += 16) {
        float v0 = (lane < NN) ? Smat[i * 52 + lane] : -3.0e38f;
        float v1 = (lane + 32 < NN) ? Smat[i * 52 + lane + 32] : -3.0e38f;
        float m = wred_max(fmaxf(v0, v1));
        float e0 = (lane < NN) ? expf(v0 - m) : 0.f;
        float e1 = (lane + 32 < NN) ? expf(v1 - m) : 0.f;
        float s = wred_sum(e0 + e1);
        float inv = 1.0f / s;
        float p0 = e0 * inv, p1 = e1 * inv;
        float rs = wred_sum(((lane < NV) ? p0 : 0.f) + ((lane + 32 < NV) ? p1 : 0.f));
        if (lane < NN) {
            Smat[i * 52 + lane] = p0;
            attn_out[(size_t)f * (NN * NN) + i * NN + lane] = p0;
        }
        if (lane + 32 < NN) {
            Smat[i * 52 + lane + 32] = p1;
            attn_out[(size_t)f * (NN * NN) + i * NN + lane + 32] = p1;
        }
        if (lane == 0) rowsum[i] = rs;
    }
    __syncthreads();

    // aggregation + residual
    for (int idx = tid; idx < NN * H4; idx += 512) {
        int i = idx >> 7, q = idx & 127;
        const float* Ar = &Smat[i * 52];
        float4 acc = make_float4(0.f, 0.f, 0.f, 0.f);
        #pragma unroll 7
        for (int j = 0; j < NV; j++) {
            float a = Ar[j];
            float4 xv = xs4[j * H4 + q];
            acc.x = fmaf(a, xv.x, acc.x);
            acc.y = fmaf(a, xv.y, acc.y);
            acc.z = fmaf(a, xv.z, acc.z);
            acc.w = fmaf(a, xv.w, acc.w);
        }
        int sel = (i < NV) ? 0 : 1;
        float rs = rowsum[i];
        float4 ev = es4[sel * H4 + q];
        acc.x = fmaf(rs, ev.x, acc.x); acc.y = fmaf(rs, ev.y, acc.y);
        acc.z = fmaf(rs, ev.z, acc.z); acc.w = fmaf(rs, ev.w, acc.w);
        float a49 = Ar[NV];
        float4 x49 = xs4[NV * H4 + q];
        float4 e2v = es4[2 * H4 + q];
        acc.x = fmaf(a49, x49.x + e2v.x, acc.x);
        acc.y = fmaf(a49, x49.y + e2v.y, acc.y);
        acc.z = fmaf(a49, x49.z + e2v.z, acc.z);
        acc.w = fmaf(a49, x49.w + e2v.w, acc.w);
        float4 xi = xs4[i * H4 + q];
        acc.x += xi.x; acc.y += xi.y; acc.z += xi.z; acc.w += xi.w;
        sp4[idx] = acc;
    }
    __syncthreads();

    // layernorm + relu per row
    for (int i = wid; i < NN; i += 16) {
        float4 v[4];
        #pragma unroll
        for (int c = 0; c < 4; c++) v[c] = sp4[i * H4 + lane + 32 * c];
        float s = 0.f;
        #pragma unroll
        for (int c = 0; c < 4; c++) s += v[c].x + v[c].y + v[c].z + v[c].w;
        float mean = wred_sum(s) * (1.0f / H_);
        float ss = 0.f;
        #pragma unroll
        for (int c = 0; c < 4; c++) {
            float dx = v[c].x - mean, dy = v[c].y - mean, dz = v[c].z - mean, dw = v[c].w - mean;
            ss += dx * dx + dy * dy + dz * dz + dw * dw;
        }
        float var = wred_sum(ss) * (1.0f / H_);
        float rstd = rsqrtf(var + 1e-5f);
        float4* og = (float4*)(spo + ((size_t)f * NN + i) * H_);
        #pragma unroll
        for (int c = 0; c < 4; c++) {
            int q = lane + 32 * c;
            float4 gv = ((const float4*)lng)[q];
            float4 bv = ((const float4*)lnb)[q];
            float4 o;
            o.x = fmaxf((v[c].x - mean) * rstd * gv.x + bv.x, 0.f);
            o.y = fmaxf((v[c].y - mean) * rstd * gv.y + bv.y, 0.f);
            o.z = fmaxf((v[c].z - mean) * rstd * gv.z + bv.z, 0.f);
            o.w = fmaxf((v[c].w - mean) * rstd * gv.w + bv.w, 0.f);
            og[q] = o;
        }
    }
}

#define ATTN_SMEM ((2 * NN * H_ + 3 * H_ + NN * 52 + 5 * NN + 3 + 1) * 4)

// ---------------------------------------------------------------------------
// cos + build P = cos*prev, S = (1-cos)*cur  as hi/lo bf16
// ---------------------------------------------------------------------------
__global__ void __launch_bounds__(256) cos_k(
    const float* __restrict__ sp, float* __restrict__ cosout,
    __nv_bfloat16* __restrict__ phi, __nv_bfloat16* __restrict__ plo,
    __nv_bfloat16* __restrict__ shi, __nv_bfloat16* __restrict__ slo)
{
    int gw = (blockIdx.x * blockDim.x + threadIdx.x) >> 5;
    int lane = threadIdx.x & 31;
    if (gw >= TROWS) return;
    int i = gw % NN;
    int bt = gw / NN;
    int b = bt / (T_ - 1);
    int tm1 = bt % (T_ - 1);
    const float4* cur  = (const float4*)(sp + ((size_t)(b * T_ + tm1 + 1) * NN + i) * H_);
    const float4* prev = (const float4*)(sp + ((size_t)(b * T_ + tm1) * NN + i) * H_);
    float dot = 0.f, na2 = 0.f, nb2 = 0.f;
    for (int q = lane; q < H4; q += 32) {
        float4 c = cur[q], p = prev[q];
        dot += dot4(c, p);
        na2 += dot4(c, c);
        nb2 += dot4(p, p);
    }
    dot = wred_sum(dot); na2 = wred_sum(na2); nb2 = wred_sum(nb2);
    float cosv = dot / (fmaxf(sqrtf(na2), 1e-8f) * fmaxf(sqrtf(nb2), 1e-8f));
    if (lane == 0) cosout[gw] = cosv;
    float omc = 1.0f - cosv;
    uint2* ph = (uint2*)phi + (size_t)gw * H4;
    uint2* pl = (uint2*)plo + (size_t)gw * H4;
    uint2* sh = (uint2*)shi + (size_t)gw * H4;
    uint2* sl = (uint2*)slo + (size_t)gw * H4;
    for (int q = lane; q < H4; q += 32) {
        float4 p = prev[q], c = cur[q];
        float4 pv = make_float4(cosv * p.x, cosv * p.y, cosv * p.z, cosv * p.w);
        float4 sv = make_float4(omc * c.x, omc * c.y, omc * c.z, omc * c.w);
        uint2 h, l;
        split4(pv, h, l); ph[q] = h; pl[q] = l;
        split4(sv, h, l); sh[q] = h; sl[q] = l;
    }
}

// ---------------------------------------------------------------------------
// assemble out_nodes + layernorm -> hi/lo bf16
// ---------------------------------------------------------------------------
__global__ void __launch_bounds__(256) assemble_k(
    const float* __restrict__ sp, const float* __restrict__ upd,
    const float* __restrict__ lng, const float* __restrict__ lnb,
    __nv_bfloat16* __restrict__ ohi, __nv_bfloat16* __restrict__ olo)
{
    int m = (blockIdx.x * blockDim.x + threadIdx.x) >> 5;
    int lane = threadIdx.x & 31;
    if (m >= ROWS) return;
    int i = m % NN;
    int t = (m / NN) % T_;
    int b = m / (NN * T_);
    const float4* s = (const float4*)(sp + (size_t)m * H_);
    float4 v[4];
    #pragma unroll
    for (int c = 0; c < 4; c++) v[c] = s[lane + 32 * c];
    if (t > 0) {
        size_t r = (size_t)(b * (T_ - 1) + (t - 1)) * NN + i;
        const float4* u = (const float4*)(upd + r * H_);
        #pragma unroll
        for (int c = 0; c < 4; c++) {
            float4 uu = u[lane + 32 * c];
            v[c].x += uu.x; v[c].y += uu.y; v[c].z += uu.z; v[c].w += uu.w;
        }
    }
    float sum = 0.f;
    #pragma unroll
    for (int c = 0; c < 4; c++) sum += v[c].x + v[c].y + v[c].z + v[c].w;
    float mean = wred_sum(sum) * (1.0f / H_);
    float ss = 0.f;
    #pragma unroll
    for (int c = 0; c < 4; c++) {
        float dx = v[c].x - mean, dy = v[c].y - mean, dz = v[c].z - mean, dw = v[c].w - mean;
        ss += dx * dx + dy * dy + dz * dz + dw * dw;
    }
    float var = wred_sum(ss) * (1.0f / H_);
    float rstd = rsqrtf(var + 1e-5f);
    uint2* oh = (uint2*)ohi + (size_t)m * H4;
    uint2* ol = (uint2*)olo + (size_t)m * H4;
    #pragma unroll
    for (int c = 0; c < 4; c++) {
        int q = lane + 32 * c;
        float4 gv = ((const float4*)lng)[q];
        float4 bv = ((const float4*)lnb)[q];
        float4 r;
        r.x = (v[c].x - mean) * rstd * gv.x + bv.x;
        r.y = (v[c].y - mean) * rstd * gv.y + bv.y;
        r.z = (v[c].z - mean) * rstd * gv.z + bv.z;
        r.w = (v[c].w - mean) * rstd * gv.w + bv.w;
        uint2 h, l;
        split4(r, h, l);
        oh[q] = h; ol[q] = l;
    }
}

// ---------------------------------------------------------------------------
// Launch
// ---------------------------------------------------------------------------
extern "C" void kernel_launch(void* const* d_in, const int* in_sizes, int n_in,
                              void* d_out, int out_size)
{
    const float* visual = (const float*)d_in[0];
    const float* audio  = (const float*)d_in[1];
    const float* in_W   = (const float*)d_in[2];
    const float* in_b   = (const float*)d_in[3];
    const float* out_W  = (const float*)d_in[4];
    const float* out_b  = (const float*)d_in[5];

    float *x, *sp, *C, *attn0, *cos0;
    __nv_bfloat16 *phi, *plo, *shi, *slo, *xhi, *xlo, *whi, *wlo;
    cudaGetSymbolAddress((void**)&x, g_x);
    cudaGetSymbolAddress((void**)&sp, g_sp);
    cudaGetSymbolAddress((void**)&C, g_C);
    cudaGetSymbolAddress((void**)&phi, g_phi);
    cudaGetSymbolAddress((void**)&plo, g_plo);
    cudaGetSymbolAddress((void**)&shi, g_shi);
    cudaGetSymbolAddress((void**)&slo, g_slo);
    cudaGetSymbolAddress((void**)&xhi, g_xhi);
    cudaGetSymbolAddress((void**)&xlo, g_xlo);
    cudaGetSymbolAddress((void**)&whi, g_whi);
    cudaGetSymbolAddress((void**)&wlo, g_wlo);
    cudaGetSymbolAddress((void**)&attn0, g_attn0);
    cudaGetSymbolAddress((void**)&cos0, g_cos0);

    cudaFuncSetAttribute(attn_k, cudaFuncAttributeMaxDynamicSharedMemorySize, ATTN_SMEM);
    cudaFuncSetAttribute((const void*)mmagemm_k<0, false>, cudaFuncAttributeMaxDynamicSharedMemorySize, GS_SMEM);
    cudaFuncSetAttribute((const void*)mmagemm_k<1, false>, cudaFuncAttributeMaxDynamicSharedMemorySize, GS_SMEM);
    cudaFuncSetAttribute((const void*)mmagemm_k<2, false>, cudaFuncAttributeMaxDynamicSharedMemorySize, GS_SMEM);
    cudaFuncSetAttribute((const void*)mmagemm_k<3, true>,  cudaFuncAttributeMaxDynamicSharedMemorySize, GS_SMEM);

    float* outp = (float*)d_out;

    dim3 gfull(4, (ROWS + 127) / 128);
    dim3 gtemp(4, (TROWS + 127) / 128);
    const int HH4 = (H_ * H_) / 4;

    // weight splits (order: in, Wc0, Ws0, Wo0, Wc1, Ws1, Wo1, out) — one launch
    {
        WPtrs wp;
        wp.p[0] = in_W;
        wp.p[1] = (const float*)d_in[9];
        wp.p[2] = (const float*)d_in[11];
        wp.p[3] = (const float*)d_in[13];
        wp.p[4] = (const float*)d_in[17];
        wp.p[5] = (const float*)d_in[19];
        wp.p[6] = (const float*)d_in[21];
        wp.p[7] = out_W;
        convw_k<<<(8 * HH4 + 255) / 256, 256>>>(wp, whi, wlo);
    }

    // input projection
    {
        int nblk = (ROWS * H4 + 255) / 256;
        gather_k<<<nblk, 256>>>(visual, audio, phi, plo);
        mmagemm_k<0, false><<<gfull, 256, GS_SMEM>>>(
            phi, plo, whi + 0 * (size_t)H_ * H_, wlo + 0 * (size_t)H_ * H_,
            in_b, nullptr, x, nullptr, nullptr, ROWS);
    }

    for (int layer = 0; layer < 2; layer++) {
        const float* edge = (const float*)d_in[6 + 8 * layer];
        const float* lng  = (const float*)d_in[7 + 8 * layer];
        const float* lnb  = (const float*)d_in[8 + 8 * layer];
        const float* bc   = (const float*)d_in[10 + 8 * layer];
        const float* bs   = (const float*)d_in[12 + 8 * layer];
        const size_t wofs = (size_t)(1 + 3 * layer) * H_ * H_;   // Wc
        const size_t wofs2 = wofs + (size_t)H_ * H_;             // Ws
        const size_t wofs3 = wofs2 + (size_t)H_ * H_;            // Wo

        float* attn_out = (layer == 1) ? (outp + OUT_MAIN) : attn0;
        float* cos_out  = (layer == 1) ? (outp + OUT_MAIN + OUT_ATTN) : cos0;

        attn_k<<<FRAMES, 512, ATTN_SMEM>>>(x, edge, lng, lnb, sp, attn_out);

        {
            int nblk = (TROWS * 32 + 255) / 256;
            cos_k<<<nblk, 256>>>(sp, cos_out, phi, plo, shi, slo);
        }

        mmagemm_k<1, false><<<gtemp, 256, GS_SMEM>>>(
            phi, plo, whi + wofs, wlo + wofs, bc, nullptr, C, nullptr, nullptr, TROWS);
        mmagemm_k<2, false><<<gtemp, 256, GS_SMEM>>>(
            shi, slo, whi + wofs2, wlo + wofs2, bs, C, C, nullptr, nullptr, TROWS);

        {
            int nblk = (ROWS * 32 + 255) / 256;
            assemble_k<<<nblk, 256>>>(sp, C, lng, lnb, phi, plo);
        }

        mmagemm_k<3, true><<<gfull, 256, GS_SMEM>>>(
            phi, plo, whi + wofs3, wlo + wofs3, nullptr, x, x, xhi, xlo, ROWS);
    }

    // output projection
    mmagemm_k<0, false><<<gfull, 256, GS_SMEM>>>(
        xhi, xlo, whi + 7 * (size_t)H_ * H_, wlo + 7 * (size_t)H_ * H_,
        out_b, nullptr, outp, nullptr, nullptr, ROWS);

    (void)in_sizes; (void)n_in; (void)out_size;
}